// round 10
// baseline (speedup 1.0000x reference)
#include <cuda_runtime.h>
#include <cuda_fp16.h>
#include <math.h>
#include <stdint.h>

// Problem constants
#define BB   2
#define SS   2048
#define DD   768
#define HH   12
#define VV   50257
#define FFD  3072
#define HDIM 64
#define NTOK (BB*SS)
#define VPAD 50304            // 393*128, multiple of 128

// ---------------------------------------------------------------------------
// Scratch (static device globals -- no allocation allowed)
// ---------------------------------------------------------------------------
__device__ float g_x   [NTOK*DD];      // embeddings + PE (residual for step 4)
__device__ float g_mha [NTOK*DD];
__device__ float g_h1  [NTOK*DD];      // LN1 out fp32 (residual for step 7)
__device__ float g_ffo [NTOK*DD];
__device__ float g_pebase[DD];         // 10000^(-2d/D)

// fp16 activations (A operands, single-term)
__device__ __half g_xh [NTOK*DD];
__device__ __half g_ath[NTOK*DD];
__device__ __half g_h1h[NTOK*DD];
__device__ __half g_ffh[NTOK*FFD];
__device__ __half g_h2h[NTOK*DD];

// head-major attention operands [b][h][s][64]
__device__ __half g_qh[NTOK*DD];
__device__ __half g_kh[NTOK*DD];
__device__ __half g_vh[NTOK*DD];

// fp16 weights, natural [K, Npad] layout (convert-only, NO transpose)
__device__ __half g_wqkv[DD * 3*DD];
__device__ __half g_wsum[DD * DD];
__device__ __half g_wff1[(size_t)DD * FFD];
__device__ __half g_wff2[(size_t)FFD * DD];
__device__ __half g_wout[(size_t)DD * VPAD];

// ---------------------------------------------------------------------------
// PTX helpers (plain sm_103-safe: cp.async, ldmatrix, mma.sync only)
// ---------------------------------------------------------------------------
__device__ __forceinline__ uint32_t smem_u32(const void* p) {
    uint32_t a;
    asm("{ .reg .u64 t; cvta.to.shared.u64 t, %1; cvt.u32.u64 %0, t; }"
        : "=r"(a) : "l"(p));
    return a;
}

#define CP16(dst, src) \
    asm volatile("cp.async.cg.shared.global [%0], [%1], 16;" \
                 :: "r"(dst), "l"(src) : "memory")
#define CP_COMMIT() asm volatile("cp.async.commit_group;" ::: "memory")
#define CP_WAIT1()  asm volatile("cp.async.wait_group 1;"  ::: "memory")
#define CP_WAIT0()  asm volatile("cp.async.wait_group 0;"  ::: "memory")

#define LDSM4(r, a) \
    asm volatile("ldmatrix.sync.aligned.m8n8.x4.shared.b16 {%0,%1,%2,%3}, [%4];" \
        : "=r"((r)[0]), "=r"((r)[1]), "=r"((r)[2]), "=r"((r)[3]) : "r"(a))

#define LDSM4T(r, a) \
    asm volatile("ldmatrix.sync.aligned.m8n8.x4.trans.shared.b16 {%0,%1,%2,%3}, [%4];" \
        : "=r"((r)[0]), "=r"((r)[1]), "=r"((r)[2]), "=r"((r)[3]) : "r"(a))

#define MMAH(d, a, b0, b1) \
    asm volatile("mma.sync.aligned.m16n8k16.row.col.f32.f16.f16.f32 " \
        "{%0,%1,%2,%3}, {%4,%5,%6,%7}, {%8,%9}, {%0,%1,%2,%3};" \
        : "+f"((d)[0]), "+f"((d)[1]), "+f"((d)[2]), "+f"((d)[3]) \
        : "r"((a)[0]), "r"((a)[1]), "r"((a)[2]), "r"((a)[3]), \
          "r"(b0), "r"(b1))

__device__ __forceinline__ uint32_t f22u(float a, float b) {
    __half2 t = __floats2half2_rn(a, b);
    return *reinterpret_cast<uint32_t*>(&t);
}

// ---------------------------------------------------------------------------
// Single-term fp16 mma.sync GEMM: C[M,N] = A[M,K] @ B[K,N]
// A: [M,K] fp16 (80B smem rows, LDSM4).  B: [K,Npad] fp16 (256B smem rows,
// LDSM4T trans fragments -- same pattern as attention PV).
// Template MT: per-warp m-subtiles (4 -> CTA 128xN, 2 -> CTA 64xN).
// 8 warps (2m x 4n), BK=32, cp.async double-buffer.
// mode: 1=+bias, 2=relu, 4=+Res, 8=QKV head-major scatter
// ---------------------------------------------------------------------------
#define SMS 80
#define BSS 272                           // B smem row stride (256 + 16 pad)

template<int MT>
__global__ __launch_bounds__(256, 1) void tgemm_k(
    const uint4* __restrict__ Ah, const uint4* __restrict__ Bt,
    const float* __restrict__ bias, const float* __restrict__ Res,
    float* __restrict__ C, __half* __restrict__ Ch,
    __half* __restrict__ K16, __half* __restrict__ V16,
    int M, int N, int K, int Npv, int mode)   // Npv = Npad/8 (uint4 per B row)
{
    constexpr int ABY = 32*MT*SMS;        // A tile bytes
    constexpr int BBY = 32*BSS;           // B tile bytes (32 k-rows x 256B)
    constexpr int BUF = ABY + BBY;

    extern __shared__ char sm[];
    const uint32_t sb = smem_u32(sm);
    const int tid  = threadIdx.x;
    const int lane = tid & 31;
    const int warp = tid >> 5;
    const int wm = warp >> 2;
    const int wn = warp & 3;
    const int m0 = blockIdx.x * (32*MT);
    const int n0 = blockIdx.y * 128;

    const int Kv  = K >> 3;
    const int nch = K >> 5;
    const int lrow = tid >> 2;
    const int lseg = tid & 3;
    const int brow = tid >> 4;            // 0..15 (B load row base, x2 iters)
    const int bseg = tid & 15;            // 0..15 uint4 per 256B row

    float acc[MT][4][4];
#pragma unroll
    for (int i = 0; i < MT; i++)
#pragma unroll
        for (int j = 0; j < 4; j++)
#pragma unroll
            for (int k = 0; k < 4; k++) acc[i][j][k] = 0.f;

    auto load_chunk = [&](int c) {
        const int b = c & 1;
        const uint32_t base = sb + b * BUF;
        const int kc4 = c << 2;           // uint4 offset in A rows
        const int kc  = c << 5;           // k base for B rows
#pragma unroll
        for (int it = 0; it < MT/2; it++) {
            int row = lrow + it * 64;
            size_t ga = (size_t)(m0 + row) * Kv + kc4 + lseg;
            CP16(base + row * SMS + lseg * 16, Ah + ga);
        }
#pragma unroll
        for (int it = 0; it < 2; it++) {
            int row = brow + it * 16;
            size_t gb = (size_t)(kc + row) * Npv + (n0 >> 3) + bseg;
            CP16(base + ABY + row * BSS + bseg * 16, Bt + gb);
        }
        CP_COMMIT();
    };

    load_chunk(0);

    for (int c = 0; c < nch; c++) {
        if (c + 1 < nch) { load_chunk(c + 1); CP_WAIT1(); }
        else             { CP_WAIT0(); }
        __syncthreads();

        const uint32_t base = sb + (c & 1) * BUF;
        const uint32_t ab = base + (wm * (16*MT) + (lane & 15)) * SMS + ((lane >> 4) << 4);
        const uint32_t bbT = base + ABY + (lane & 15) * BSS
                             + wn * 64 + ((lane >> 4) << 4);

#pragma unroll
        for (int ks = 0; ks < 2; ks++) {
            const uint32_t ko = ks << 5;
            uint32_t ahf[MT*4], bf[8];
#pragma unroll
            for (int mt = 0; mt < MT; mt++)
                LDSM4(&ahf[mt*4], ab + mt * (16*SMS) + ko);
            LDSM4T(&bf[0], bbT + ks * (16*BSS));
            LDSM4T(&bf[4], bbT + ks * (16*BSS) + 32);
#pragma unroll
            for (int mt = 0; mt < MT; mt++)
#pragma unroll
                for (int nt = 0; nt < 4; nt++) {
                    const int bi = (nt >> 1) * 4 + ((nt & 1) << 1);
                    MMAH(acc[mt][nt], &ahf[mt*4], bf[bi], bf[bi+1]);
                }
        }
        __syncthreads();
    }

    // epilogue
#pragma unroll
    for (int mt = 0; mt < MT; mt++) {
        const int row0 = m0 + wm * (16*MT) + mt * 16 + (lane >> 2);
#pragma unroll
        for (int nt = 0; nt < 4; nt++) {
            const int col = n0 + wn * 32 + nt * 8 + ((lane & 3) << 1);
            if (col >= N) continue;
            const float* d = acc[mt][nt];
#pragma unroll
            for (int h = 0; h < 2; h++) {
                const int r = row0 + h * 8;
                size_t o = (size_t)r * N + col;
#pragma unroll
                for (int j = 0; j < 2; j++) {
                    if (col + j >= N) break;
                    float x = d[h*2+j];
                    if (mode & 1) x += bias[col+j];
                    if (mode & 4) x += Res[o+j];
                    if (mode & 2) x = fmaxf(x, 0.f);
                    if (mode & 8) {
                        // head-major scatter: [b][head][s][64]
                        int cc = col + j;
                        int bq = r >> 11, sq = r & 2047;
                        int part = cc / DD;          // 0=Q 1=K 2=V
                        int cd = cc - part * DD;
                        int hd = cd >> 6, dd = cd & 63;
                        size_t oo = (((size_t)(bq*HH + hd))*SS + sq)*64 + dd;
                        __half hv = __float2half_rn(x);
                        if (part == 0)      Ch[oo]  = hv;
                        else if (part == 1) K16[oo] = hv;
                        else                V16[oo] = hv;
                    } else {
                        if (C)  C[o+j] = x;
                        if (Ch) Ch[o+j] = __float2half_rn(x);
                    }
                }
            }
        }
    }
}

// ---------------------------------------------------------------------------
// Streaming weight convert (no transpose): W[K,N] fp32 -> T[K,Npad] fp16.
// grid (ceil(Npad/2048), K); thread: 8 consecutive n, one 16B store.
// Pad columns (n >= N) are zero-filled.
// ---------------------------------------------------------------------------
__global__ __launch_bounds__(256) void wcv_k(const float* __restrict__ W,
                                             __half* __restrict__ T,
                                             int K, int N, int Npad)
{
    int n8 = blockIdx.x * 256 + threadIdx.x;
    if (n8 >= (Npad >> 3)) return;
    int k = blockIdx.y;
    int n = n8 << 3;
    const float* wr = W + (size_t)k * N + n;
    __half h[8];
#pragma unroll
    for (int j = 0; j < 8; j++)
        h[j] = (n + j < N) ? __float2half_rn(wr[j]) : __half(0.f);
    *(uint4*)&T[(size_t)k * Npad + n] = *(uint4*)h;
}

// ---------------------------------------------------------------------------
// W_o head-block sum (no transpose): T[r,c] = fp16(sum_h Wo[h*D + r, c])
// ---------------------------------------------------------------------------
__global__ __launch_bounds__(256) void wosum_k(const float* __restrict__ Wo,
                                               __half* __restrict__ T)
{
    int i = blockIdx.x * 256 + threadIdx.x;     // 768*96 threads
    int r = i / 96;
    int c = (i % 96) << 3;
    float s[8];
#pragma unroll
    for (int j = 0; j < 8; j++) s[j] = 0.f;
#pragma unroll
    for (int h = 0; h < HH; h++) {
        const float* row = Wo + ((size_t)(h * DD + r)) * DD + c;
#pragma unroll
        for (int j = 0; j < 8; j++) s[j] += row[j];
    }
    __half hv[8];
#pragma unroll
    for (int j = 0; j < 8; j++) hv[j] = __float2half_rn(s[j]);
    *(uint4*)&T[(size_t)r * DD + c] = *(uint4*)hv;
}

// ---------------------------------------------------------------------------
// PE frequency table:  pebase[d] = 10000^(-2d/D)
// ---------------------------------------------------------------------------
__global__ void pebase_k(float* __restrict__ pb)
{
    int d = blockIdx.x * 256 + threadIdx.x;
    if (d < DD) pb[d] = powf(10000.0f, -2.0f * (float)d / (float)DD);
}

// ---------------------------------------------------------------------------
// Embedding + positional encoding, fused fp16 convert
// ---------------------------------------------------------------------------
__global__ __launch_bounds__(256) void embed_k(const int* __restrict__ ids,
                                               const float* __restrict__ emb,
                                               const float* __restrict__ pb,
                                               float* __restrict__ x,
                                               __half* __restrict__ xh)
{
    int t = blockIdx.x;
    int s = t % SS;
    int id = ids[t];
    const float* er = emb + (size_t)id * DD;
    size_t base = (size_t)t * DD;
    for (int d = threadIdx.x; d < DD; d += 256) {
        float ang = (float)s * pb[d];
        float pe  = (d & 1) ? cosf(ang) : sinf(ang);
        float v = er[d] + pe;
        x[base + d] = v;
        xh[base + d] = __float2half_rn(v);
    }
}

// ---------------------------------------------------------------------------
// Tensor-core causal flash attention (FA2 style), single-term fp16 Q/K/V/P.
// grid (S/64, H, B), 128 threads (4 warps x 16 Q rows). Heavy tiles first.
// ---------------------------------------------------------------------------
#define SMSA 144
#define ATILE 9216          // 64*144
#define ASM_TOTAL (5*ATILE) // 46080  (Q, K x2, V x2)

__global__ __launch_bounds__(128, 1) void attn_k(
    const __half* __restrict__ Qh,
    const __half* __restrict__ Kh, const __half* __restrict__ Vh,
    __half* __restrict__ oh)
{
    extern __shared__ char sm[];
    const uint32_t sb = smem_u32(sm);
    const int qb = gridDim.x - 1 - blockIdx.x;   // heavy tiles first
    const int hh = blockIdx.y, bb = blockIdx.z;
    const int tid = threadIdx.x, lane = tid & 31, warp = tid >> 5;
    const size_t hbase = ((size_t)(bb*HH + hh)) * SS * 64;

    const uint32_t sQ  = sb;
    const uint32_t sK0 = sb + ATILE;
    const uint32_t sV0 = sb + 3*ATILE;

    for (int idx = tid; idx < 512; idx += 128) {
        int r = idx >> 3, seg = idx & 7;
        size_t g = hbase + (size_t)(qb*64 + r)*64 + seg*8;
        CP16(sQ + r*SMSA + seg*16, (const uint4*)(Qh + g));
    }
    CP_COMMIT();

    auto loadKV = [&](int j) {
        uint32_t kb = sK0 + (j & 1)*ATILE;
        uint32_t vb = sV0 + (j & 1)*ATILE;
        for (int idx = tid; idx < 512; idx += 128) {
            int r = idx >> 3, seg = idx & 7;
            size_t g = hbase + (size_t)(j*64 + r)*64 + seg*8;
            CP16(kb + r*SMSA + seg*16, (const uint4*)(Kh + g));
            CP16(vb + r*SMSA + seg*16, (const uint4*)(Vh + g));
        }
        CP_COMMIT();
    };

    loadKV(0);

    uint32_t qf[4][4];
    float oacc[8][4];
    float m[2] = {-1e30f, -1e30f}, l[2] = {0.f, 0.f};
#pragma unroll
    for (int nt = 0; nt < 8; nt++)
#pragma unroll
        for (int j2 = 0; j2 < 4; j2++) oacc[nt][j2] = 0.f;

    const int rowg = lane >> 2;
    const int colg = (lane & 3) << 1;
    const uint32_t aoff = (warp*16 + (lane & 15))*SMSA + ((lane >> 4) << 4);

    for (int j = 0; j <= qb; j++) {
        if (j < qb) loadKV(j + 1);
        if (j < qb) CP_WAIT1(); else CP_WAIT0();
        __syncthreads();

        if (j == 0) {
#pragma unroll
            for (int kk = 0; kk < 4; kk++)
                LDSM4(qf[kk], sQ + aoff + kk*32);
        }

        const uint32_t kb = sK0 + (j & 1)*ATILE;
        const uint32_t vb = sV0 + (j & 1)*ATILE;

        float sacc[8][4];
#pragma unroll
        for (int nt = 0; nt < 8; nt++)
#pragma unroll
            for (int j2 = 0; j2 < 4; j2++) sacc[nt][j2] = 0.f;

#pragma unroll
        for (int kk = 0; kk < 4; kk++) {
            uint32_t bf[16];
#pragma unroll
            for (int q = 0; q < 4; q++)
                LDSM4(&bf[q*4], kb + (q*16 + (lane & 15))*SMSA
                                  + ((lane >> 4) << 4) + kk*32);
#pragma unroll
            for (int nt = 0; nt < 8; nt++) {
                const int q = (nt >> 1)*4, r = nt & 1;
                MMAH(sacc[nt], qf[kk], bf[q+r], bf[q+2+r]);
            }
        }

        const int grow0 = qb*64 + warp*16 + rowg;
#pragma unroll
        for (int nt = 0; nt < 8; nt++)
#pragma unroll
            for (int j2 = 0; j2 < 4; j2++) {
                float s = sacc[nt][j2] * 0.125f;
                if (j == qb) {
                    int gc = j*64 + nt*8 + colg + (j2 & 1);
                    int gr = grow0 + ((j2 >> 1) << 3);
                    if (gc > gr) s = -1e30f;
                }
                sacc[nt][j2] = s;
            }

        float mt[2] = {-1e30f, -1e30f};
#pragma unroll
        for (int nt = 0; nt < 8; nt++) {
            mt[0] = fmaxf(mt[0], fmaxf(sacc[nt][0], sacc[nt][1]));
            mt[1] = fmaxf(mt[1], fmaxf(sacc[nt][2], sacc[nt][3]));
        }
#pragma unroll
        for (int i = 0; i < 2; i++) {
            mt[i] = fmaxf(mt[i], __shfl_xor_sync(0xFFFFFFFFu, mt[i], 1));
            mt[i] = fmaxf(mt[i], __shfl_xor_sync(0xFFFFFFFFu, mt[i], 2));
        }
        float corr[2], mnew[2];
#pragma unroll
        for (int i = 0; i < 2; i++) {
            mnew[i] = fmaxf(m[i], mt[i]);
            corr[i] = __expf(m[i] - mnew[i]);
            m[i] = mnew[i];
        }
        float ls[2] = {0.f, 0.f};
#pragma unroll
        for (int nt = 0; nt < 8; nt++) {
            sacc[nt][0] = __expf(sacc[nt][0] - mnew[0]);
            sacc[nt][1] = __expf(sacc[nt][1] - mnew[0]);
            sacc[nt][2] = __expf(sacc[nt][2] - mnew[1]);
            sacc[nt][3] = __expf(sacc[nt][3] - mnew[1]);
            ls[0] += sacc[nt][0] + sacc[nt][1];
            ls[1] += sacc[nt][2] + sacc[nt][3];
        }
#pragma unroll
        for (int i = 0; i < 2; i++) {
            ls[i] += __shfl_xor_sync(0xFFFFFFFFu, ls[i], 1);
            ls[i] += __shfl_xor_sync(0xFFFFFFFFu, ls[i], 2);
            l[i] = l[i]*corr[i] + ls[i];
        }
#pragma unroll
        for (int nt = 0; nt < 8; nt++) {
            oacc[nt][0] *= corr[0]; oacc[nt][1] *= corr[0];
            oacc[nt][2] *= corr[1]; oacc[nt][3] *= corr[1];
        }

#pragma unroll
        for (int kt = 0; kt < 4; kt++) {
            uint32_t pa[4];
            pa[0] = f22u(sacc[2*kt  ][0], sacc[2*kt  ][1]);
            pa[1] = f22u(sacc[2*kt  ][2], sacc[2*kt  ][3]);
            pa[2] = f22u(sacc[2*kt+1][0], sacc[2*kt+1][1]);
            pa[3] = f22u(sacc[2*kt+1][2], sacc[2*kt+1][3]);
            uint32_t vf[16];
#pragma unroll
            for (int q = 0; q < 4; q++)
                LDSM4T(&vf[q*4], vb + (kt*16 + (lane & 15))*SMSA
                                    + q*32 + ((lane >> 4) << 4));
#pragma unroll
            for (int nt = 0; nt < 8; nt++) {
                const int base = (nt >> 1)*4 + ((nt & 1) << 1);
                MMAH(oacc[nt], pa, vf[base], vf[base+1]);
            }
        }
        __syncthreads();
    }

    float inv[2] = {1.f / l[0], 1.f / l[1]};
#pragma unroll
    for (int nt = 0; nt < 8; nt++)
#pragma unroll
        for (int j2 = 0; j2 < 4; j2++) {
            int srow = qb*64 + warp*16 + rowg + ((j2 >> 1) << 3);
            int tok = bb*SS + srow;
            int col = hh*64 + nt*8 + colg + (j2 & 1);
            oh[(size_t)tok*DD + col] =
                __float2half_rn(oacc[nt][j2] * inv[j2 >> 1]);
        }
}

// ---------------------------------------------------------------------------
// LayerNorm over D=768, optional fp32 out + fp16 out
// ---------------------------------------------------------------------------
__global__ __launch_bounds__(256) void layernorm_k(const float* __restrict__ X,
                                                   const float* __restrict__ g,
                                                   const float* __restrict__ b,
                                                   float* __restrict__ Y,
                                                   __half* __restrict__ Yh)
{
    int t = blockIdx.x;
    const float* xr = X + (size_t)t * DD;
    float vals[3];
    float s = 0.f, s2 = 0.f;
#pragma unroll
    for (int i = 0; i < 3; i++) {
        float v = xr[threadIdx.x + i * 256];
        vals[i] = v;
        s += v; s2 += v * v;
    }
#pragma unroll
    for (int o = 16; o > 0; o >>= 1) {
        s  += __shfl_xor_sync(0xFFFFFFFFu, s,  o);
        s2 += __shfl_xor_sync(0xFFFFFFFFu, s2, o);
    }
    __shared__ float rs[8], rs2[8];
    int w = threadIdx.x >> 5;
    if ((threadIdx.x & 31) == 0) { rs[w] = s; rs2[w] = s2; }
    __syncthreads();
    if (threadIdx.x < 32) {
        s  = (threadIdx.x < 8) ? rs [threadIdx.x] : 0.f;
        s2 = (threadIdx.x < 8) ? rs2[threadIdx.x] : 0.f;
#pragma unroll
        for (int o = 4; o > 0; o >>= 1) {
            s  += __shfl_xor_sync(0xFFFFFFFFu, s,  o);
            s2 += __shfl_xor_sync(0xFFFFFFFFu, s2, o);
        }
        if (threadIdx.x == 0) { rs[0] = s; rs2[0] = s2; }
    }
    __syncthreads();
    float mean = rs[0] * (1.f / DD);
    float var  = rs2[0] * (1.f / DD) - mean * mean;
    float rstd = rsqrtf(var + 1e-5f);
#pragma unroll
    for (int i = 0; i < 3; i++) {
        int d = threadIdx.x + i * 256;
        float v = (vals[i] - mean) * rstd * g[d] + b[d];
        size_t o = (size_t)t * DD + d;
        if (Y)  Y[o] = v;
        Yh[o] = __float2half_rn(v);
    }
}

// ---------------------------------------------------------------------------
// Launch
// ---------------------------------------------------------------------------
template<int MT>
static inline void run_gemm(const __half* Ah, const __half* Bt,
                            const float* bias, const float* Res,
                            float* C, __half* Ch, __half* K16, __half* V16,
                            int M, int N, int K, int Npad, int mode)
{
    dim3 grid(M / (32*MT), (N + 127) / 128);
    int smem = 2 * (32*MT*SMS + 32*BSS);
    tgemm_k<MT><<<grid, 256, smem>>>((const uint4*)Ah, (const uint4*)Bt,
                                     bias, Res, C, Ch, K16, V16,
                                     M, N, K, Npad >> 3, mode);
}

extern "C" void kernel_launch(void* const* d_in, const int* in_sizes, int n_in,
                              void* d_out, int out_size)
{
    const int*   ids    = (const int*)  d_in[0];
    const float* emb    = (const float*)d_in[1];
    const float* W_qkv  = (const float*)d_in[2];
    const float* b_qkv  = (const float*)d_in[3];
    const float* W_o    = (const float*)d_in[4];
    const float* b_o    = (const float*)d_in[5];
    const float* ln1_g  = (const float*)d_in[6];
    const float* ln1_b  = (const float*)d_in[7];
    const float* W_ff1  = (const float*)d_in[8];
    const float* b_ff1  = (const float*)d_in[9];
    const float* W_ff2  = (const float*)d_in[10];
    const float* b_ff2  = (const float*)d_in[11];
    const float* ln2_g  = (const float*)d_in[12];
    const float* ln2_b  = (const float*)d_in[13];
    const float* W_out  = (const float*)d_in[14];
    const float* b_out  = (const float*)d_in[15];
    float* out = (float*)d_out;

    cudaFuncSetAttribute(tgemm_k<4>, cudaFuncAttributeMaxDynamicSharedMemorySize,
                         2*(128*SMS + 32*BSS));
    cudaFuncSetAttribute(tgemm_k<2>, cudaFuncAttributeMaxDynamicSharedMemorySize,
                         2*(64*SMS + 32*BSS));
    cudaFuncSetAttribute(attn_k, cudaFuncAttributeMaxDynamicSharedMemorySize,
                         ASM_TOTAL);

    float *px, *pmha, *ph1, *pffo, *ppb;
    cudaGetSymbolAddress((void**)&px,   g_x);
    cudaGetSymbolAddress((void**)&pmha, g_mha);
    cudaGetSymbolAddress((void**)&ph1,  g_h1);
    cudaGetSymbolAddress((void**)&pffo, g_ffo);
    cudaGetSymbolAddress((void**)&ppb,  g_pebase);

    __half *xh,*ath,*h1h,*ffh,*h2h;
    cudaGetSymbolAddress((void**)&xh,  g_xh);
    cudaGetSymbolAddress((void**)&ath, g_ath);
    cudaGetSymbolAddress((void**)&h1h, g_h1h);
    cudaGetSymbolAddress((void**)&ffh, g_ffh);
    cudaGetSymbolAddress((void**)&h2h, g_h2h);

    __half *qh,*kh,*vh;
    cudaGetSymbolAddress((void**)&qh, g_qh);
    cudaGetSymbolAddress((void**)&kh, g_kh);
    cudaGetSymbolAddress((void**)&vh, g_vh);

    __half *wq,*ws,*w1,*w2,*wo;
    cudaGetSymbolAddress((void**)&wq, g_wqkv);
    cudaGetSymbolAddress((void**)&ws, g_wsum);
    cudaGetSymbolAddress((void**)&w1, g_wff1);
    cudaGetSymbolAddress((void**)&w2, g_wff2);
    cudaGetSymbolAddress((void**)&wo, g_wout);

    // Weight prep: streaming fp32->fp16 converts (no transpose)
    wcv_k<<<dim3((3*DD/8 + 255)/256, DD), 256>>>(W_qkv, wq, DD, 3*DD, 3*DD);
    wosum_k<<<(DD*96 + 255)/256, 256>>>(W_o, ws);
    wcv_k<<<dim3((FFD/8 + 255)/256, DD), 256>>>(W_ff1, w1, DD, FFD, FFD);
    wcv_k<<<dim3((DD/8 + 255)/256, FFD), 256>>>(W_ff2, w2, FFD, DD, DD);
    wcv_k<<<dim3((VPAD/8 + 255)/256, DD), 256>>>(W_out, wo, DD, VV, VPAD);

    // 1. embeddings + PE
    pebase_k<<<3, 256>>>(ppb);
    embed_k<<<NTOK, 256>>>(ids, emb, ppb, px, xh);

    // 2. QKV projection -> head-major fp16 Q, K, V
    run_gemm<4>(xh, wq, b_qkv, nullptr,
                nullptr, qh, kh, vh,
                NTOK, 3*DD, DD, 3*DD, 1|8);

    // 3. tensor-core flash attention (heavy-first scheduling)
    attn_k<<<dim3(SS/64, HH, BB), 128, ASM_TOTAL>>>(qh, kh, vh, ath);

    // 4. mha = attn @ Wsum + b_o + x  (M64 tiles)
    run_gemm<2>(ath, ws, b_o, px,
                pmha, nullptr, nullptr, nullptr,
                NTOK, DD, DD, DD, 1|4);

    // 5. LN1 (fp32 residual + fp16 out)
    layernorm_k<<<NTOK, 256>>>(pmha, ln1_g, ln1_b, ph1, h1h);

    // 6. FF1 + relu (fp16 out)
    run_gemm<4>(h1h, w1, b_ff1, nullptr,
                nullptr, ffh, nullptr, nullptr,
                NTOK, FFD, DD, FFD, 1|2);

    // 7. FF2 + residual (fp32 out; M64 tiles)
    run_gemm<2>(ffh, w2, b_ff2, ph1,
                pffo, nullptr, nullptr, nullptr,
                NTOK, DD, FFD, DD, 1|4);

    // 8. LN2 (fp16 out)
    layernorm_k<<<NTOK, 256>>>(pffo, ln2_g, ln2_b, nullptr, h2h);

    // 9. vocab projection (B padded to VPAD)
    run_gemm<4>(h2h, wo, b_out, nullptr,
                out, nullptr, nullptr, nullptr,
                NTOK, VV, DD, VPAD, 1);
}

// round 11
// speedup vs baseline: 1.2220x; 1.2220x over previous
#include <cuda_runtime.h>
#include <cuda_fp16.h>
#include <math.h>
#include <stdint.h>

// Problem constants
#define BB   2
#define SS   2048
#define DD   768
#define HH   12
#define VV   50257
#define FFD  3072
#define HDIM 64
#define NTOK (BB*SS)

// ---------------------------------------------------------------------------
// Scratch (static device globals -- no allocation allowed)
// ---------------------------------------------------------------------------
__device__ float g_x   [NTOK*DD];      // embeddings + PE (residual for step 4)
__device__ float g_mha [NTOK*DD];
__device__ float g_h1  [NTOK*DD];      // LN1 out fp32 (residual for step 7)
__device__ float g_ffo [NTOK*DD];
__device__ float g_pebase[DD];         // 10000^(-2d/D)

// fp16 activations (A operands, single-term)
__device__ __half g_xh [NTOK*DD];
__device__ __half g_ath[NTOK*DD];
__device__ __half g_h1h[NTOK*DD];
__device__ __half g_ffh[NTOK*FFD];
__device__ __half g_h2h[NTOK*DD];

// head-major attention operands [b][h][s][64]
__device__ __half g_qh[NTOK*DD];
__device__ __half g_kh[NTOK*DD];
__device__ __half g_vh[NTOK*DD];

// fp16 transposed weights [N,K]
__device__ __half g_wqkvT[3*DD*DD];
__device__ __half g_wsumT[DD*DD];
__device__ __half g_wff1T[(size_t)FFD*DD];
__device__ __half g_wff2T[(size_t)DD*FFD];
__device__ __half g_woutT[(size_t)VV*DD];

// ---------------------------------------------------------------------------
// PTX helpers (plain sm_103-safe: cp.async, ldmatrix, mma.sync only)
// ---------------------------------------------------------------------------
__device__ __forceinline__ uint32_t smem_u32(const void* p) {
    uint32_t a;
    asm("{ .reg .u64 t; cvta.to.shared.u64 t, %1; cvt.u32.u64 %0, t; }"
        : "=r"(a) : "l"(p));
    return a;
}

#define CP16(dst, src) \
    asm volatile("cp.async.cg.shared.global [%0], [%1], 16;" \
                 :: "r"(dst), "l"(src) : "memory")
#define CP_COMMIT() asm volatile("cp.async.commit_group;" ::: "memory")
#define CP_WAIT1()  asm volatile("cp.async.wait_group 1;"  ::: "memory")
#define CP_WAIT0()  asm volatile("cp.async.wait_group 0;"  ::: "memory")

#define LDSM4(r, a) \
    asm volatile("ldmatrix.sync.aligned.m8n8.x4.shared.b16 {%0,%1,%2,%3}, [%4];" \
        : "=r"((r)[0]), "=r"((r)[1]), "=r"((r)[2]), "=r"((r)[3]) : "r"(a))

#define LDSM4T(r, a) \
    asm volatile("ldmatrix.sync.aligned.m8n8.x4.trans.shared.b16 {%0,%1,%2,%3}, [%4];" \
        : "=r"((r)[0]), "=r"((r)[1]), "=r"((r)[2]), "=r"((r)[3]) : "r"(a))

#define MMAH(d, a, b0, b1) \
    asm volatile("mma.sync.aligned.m16n8k16.row.col.f32.f16.f16.f32 " \
        "{%0,%1,%2,%3}, {%4,%5,%6,%7}, {%8,%9}, {%0,%1,%2,%3};" \
        : "+f"((d)[0]), "+f"((d)[1]), "+f"((d)[2]), "+f"((d)[3]) \
        : "r"((a)[0]), "r"((a)[1]), "r"((a)[2]), "r"((a)[3]), \
          "r"(b0), "r"(b1))

__device__ __forceinline__ uint32_t f22u(float a, float b) {
    __half2 t = __floats2half2_rn(a, b);
    return *reinterpret_cast<uint32_t*>(&t);
}

// ---------------------------------------------------------------------------
// Single-term fp16 mma.sync GEMM: C[M,N] = A[M,K] @ Bt[N,K]^T
// Template MT = per-warp m-subtiles (4 -> CTA 128xN, 2 -> CTA 64xN).
// 8 warps (2m x 4n), warp tile (16*MT)x32, BK=32, cp.async double-buffer.
// SMEM row stride 80B -> conflict-free ldmatrix (all non-trans LDSM4).
// mode: 1=+bias, 2=relu, 4=+Res, 8=QKV head-major scatter
// ---------------------------------------------------------------------------
#define SMS 80

template<int MT>
__global__ __launch_bounds__(256, 1) void tgemm_k(
    const uint4* __restrict__ Ah, const uint4* __restrict__ Bt,
    const float* __restrict__ bias, const float* __restrict__ Res,
    float* __restrict__ C, __half* __restrict__ Ch,
    __half* __restrict__ K16, __half* __restrict__ V16,
    int M, int N, int K, int mode)
{
    constexpr int ABY = 32*MT*SMS;       // A tile bytes
    constexpr int BUF = ABY + 128*SMS;   // A + B per buffer

    extern __shared__ char sm[];
    const uint32_t sb = smem_u32(sm);
    const int tid  = threadIdx.x;
    const int lane = tid & 31;
    const int warp = tid >> 5;
    const int wm = warp >> 2;
    const int wn = warp & 3;
    const int m0 = blockIdx.x * (32*MT);
    const int n0 = blockIdx.y * 128;

    const int Kv  = K >> 3;
    const int nch = K >> 5;
    const int lrow = tid >> 2;
    const int lseg = tid & 3;

    float acc[MT][4][4];
#pragma unroll
    for (int i = 0; i < MT; i++)
#pragma unroll
        for (int j = 0; j < 4; j++)
#pragma unroll
            for (int k = 0; k < 4; k++) acc[i][j][k] = 0.f;

    auto load_chunk = [&](int c) {
        const int b = c & 1;
        const uint32_t base = sb + b * BUF;
        const int kc4 = c << 2;
#pragma unroll
        for (int it = 0; it < MT/2; it++) {
            int row = lrow + it * 64;
            size_t ga = (size_t)(m0 + row) * Kv + kc4 + lseg;
            CP16(base + row * SMS + lseg * 16, Ah + ga);
        }
#pragma unroll
        for (int it = 0; it < 2; it++) {
            int row = lrow + it * 64;
            int rn = n0 + row; if (rn >= N) rn = N - 1;
            size_t gb = (size_t)rn * Kv + kc4 + lseg;
            CP16(base + ABY + row * SMS + lseg * 16, Bt + gb);
        }
        CP_COMMIT();
    };

    load_chunk(0);

    for (int c = 0; c < nch; c++) {
        if (c + 1 < nch) { load_chunk(c + 1); CP_WAIT1(); }
        else             { CP_WAIT0(); }
        __syncthreads();

        const uint32_t base = sb + (c & 1) * BUF;
        const uint32_t ab = base + (wm * (16*MT) + (lane & 15)) * SMS + ((lane >> 4) << 4);
        const uint32_t bb = base + ABY + (wn * 32 + (lane & 15)) * SMS + ((lane >> 4) << 4);

#pragma unroll
        for (int ks = 0; ks < 2; ks++) {
            const uint32_t ko = ks << 5;
            uint32_t ahf[MT*4], bf[8];
#pragma unroll
            for (int mt = 0; mt < MT; mt++)
                LDSM4(&ahf[mt*4], ab + mt * (16*SMS) + ko);
#pragma unroll
            for (int q = 0; q < 2; q++)
                LDSM4(&bf[q*4], bb + q * (16*SMS) + ko);
#pragma unroll
            for (int mt = 0; mt < MT; mt++)
#pragma unroll
                for (int nt = 0; nt < 4; nt++) {
                    const int q = (nt >> 1) * 4, r = nt & 1;
                    MMAH(acc[mt][nt], &ahf[mt*4], bf[q+r], bf[q+2+r]);
                }
        }
        __syncthreads();
    }

    // epilogue
#pragma unroll
    for (int mt = 0; mt < MT; mt++) {
        const int row0 = m0 + wm * (16*MT) + mt * 16 + (lane >> 2);
#pragma unroll
        for (int nt = 0; nt < 4; nt++) {
            const int col = n0 + wn * 32 + nt * 8 + ((lane & 3) << 1);
            if (col >= N) continue;
            const float* d = acc[mt][nt];
#pragma unroll
            for (int h = 0; h < 2; h++) {
                const int r = row0 + h * 8;
                size_t o = (size_t)r * N + col;
#pragma unroll
                for (int j = 0; j < 2; j++) {
                    if (col + j >= N) break;
                    float x = d[h*2+j];
                    if (mode & 1) x += bias[col+j];
                    if (mode & 4) x += Res[o+j];
                    if (mode & 2) x = fmaxf(x, 0.f);
                    if (mode & 8) {
                        // head-major scatter: [b][head][s][64]
                        int cc = col + j;
                        int bq = r >> 11, sq = r & 2047;
                        int part = cc / DD;          // 0=Q 1=K 2=V
                        int cd = cc - part * DD;
                        int hd = cd >> 6, dd = cd & 63;
                        size_t oo = (((size_t)(bq*HH + hd))*SS + sq)*64 + dd;
                        __half hv = __float2half_rn(x);
                        if (part == 0)      Ch[oo]  = hv;
                        else if (part == 1) K16[oo] = hv;
                        else                V16[oo] = hv;
                    } else {
                        if (C)  C[o+j] = x;
                        if (Ch) Ch[o+j] = __float2half_rn(x);
                    }
                }
            }
        }
    }
}

// ---------------------------------------------------------------------------
// PE frequency table:  pebase[d] = 10000^(-2d/D)
// ---------------------------------------------------------------------------
__global__ void pebase_k(float* __restrict__ pb)
{
    int d = blockIdx.x * 256 + threadIdx.x;
    if (d < DD) pb[d] = powf(10000.0f, -2.0f * (float)d / (float)DD);
}

// ---------------------------------------------------------------------------
// Embedding + positional encoding, fused fp16 convert
// ---------------------------------------------------------------------------
__global__ __launch_bounds__(256) void embed_k(const int* __restrict__ ids,
                                               const float* __restrict__ emb,
                                               const float* __restrict__ pb,
                                               float* __restrict__ x,
                                               __half* __restrict__ xh)
{
    int t = blockIdx.x;
    int s = t % SS;
    int id = ids[t];
    const float* er = emb + (size_t)id * DD;
    size_t base = (size_t)t * DD;
    for (int d = threadIdx.x; d < DD; d += 256) {
        float ang = (float)s * pb[d];
        float pe  = (d & 1) ? cosf(ang) : sinf(ang);
        float v = er[d] + pe;
        x[base + d] = v;
        xh[base + d] = __float2half_rn(v);
    }
}

// ---------------------------------------------------------------------------
// Weight transpose + fp16 convert: W[K,N] -> T[N,K]
// 64(k) x 64(n) tiles, [64][65] conflict-free stage, 16B vector stores
// (128B contiguous per output row). Requires K % 64 == 0 (768, 3072 ok).
// ---------------------------------------------------------------------------
__global__ __launch_bounds__(256) void wconvT_k(const float* __restrict__ W,
                                                __half* __restrict__ T,
                                                int K, int N)
{
    __shared__ float t[64][65];
    const int k0 = blockIdx.y * 64, n0 = blockIdx.x * 64;
    const int tid = threadIdx.x;

    // load 64x64 fp32 tile (coalesced 256B per warp-row; MLP=16)
#pragma unroll
    for (int it = 0; it < 16; it++) {
        int i = tid + it * 256;
        int r = i >> 6, c = i & 63;
        int n = n0 + c;
        t[r][c] = (n < N) ? W[(size_t)(k0 + r) * N + n] : 0.f;
    }
    __syncthreads();

    // store: 64 n-rows x 64 k halfs = 8 uint4 per row, 2 per thread
#pragma unroll
    for (int it = 0; it < 2; it++) {
        int i = tid + it * 256;
        int n = i >> 3, kc = (i & 7) << 3;
        if (n0 + n >= N) continue;
        __half h[8];
#pragma unroll
        for (int j = 0; j < 8; j++) h[j] = __float2half_rn(t[kc + j][n]);
        *(uint4*)&T[(size_t)(n0 + n) * K + k0 + kc] = *(uint4*)h;
    }
}

// ---------------------------------------------------------------------------
// W_o head-block sum + transpose + fp16
// ---------------------------------------------------------------------------
__global__ __launch_bounds__(256) void wosumT_k(const float* __restrict__ Wo,
                                                __half* __restrict__ T)
{
    __shared__ float t[32][33];
    int r0 = blockIdx.y * 32, c0 = blockIdx.x * 32;
    int tx = threadIdx.x & 31, ty = threadIdx.x >> 5;
#pragma unroll
    for (int i = 0; i < 4; i++) {
        int r = r0 + ty + i * 8;
        float s = 0.f;
#pragma unroll
        for (int h = 0; h < HH; h++)
            s += Wo[((size_t)(h * DD + r)) * DD + c0 + tx];
        t[ty + i * 8][tx] = s;
    }
    __syncthreads();
#pragma unroll
    for (int i = 0; i < 4; i++) {
        int cc = c0 + ty + i * 8;
        int rr = r0 + tx;
        T[(size_t)cc * DD + rr] = __float2half_rn(t[tx][ty + i * 8]);
    }
}

// ---------------------------------------------------------------------------
// Tensor-core causal flash attention (FA2 style), single-term fp16 Q/K/V/P.
// grid (S/64, H, B), 128 threads (4 warps x 16 Q rows). Heavy tiles first.
// ---------------------------------------------------------------------------
#define SMSA 144
#define ATILE 9216          // 64*144
#define ASM_TOTAL (5*ATILE) // 46080  (Q, K x2, V x2)

__global__ __launch_bounds__(128, 1) void attn_k(
    const __half* __restrict__ Qh,
    const __half* __restrict__ Kh, const __half* __restrict__ Vh,
    __half* __restrict__ oh)
{
    extern __shared__ char sm[];
    const uint32_t sb = smem_u32(sm);
    const int qb = gridDim.x - 1 - blockIdx.x;   // heavy tiles first
    const int hh = blockIdx.y, bb = blockIdx.z;
    const int tid = threadIdx.x, lane = tid & 31, warp = tid >> 5;
    const size_t hbase = ((size_t)(bb*HH + hh)) * SS * 64;

    const uint32_t sQ  = sb;
    const uint32_t sK0 = sb + ATILE;
    const uint32_t sV0 = sb + 3*ATILE;

    for (int idx = tid; idx < 512; idx += 128) {
        int r = idx >> 3, seg = idx & 7;
        size_t g = hbase + (size_t)(qb*64 + r)*64 + seg*8;
        CP16(sQ + r*SMSA + seg*16, (const uint4*)(Qh + g));
    }
    CP_COMMIT();

    auto loadKV = [&](int j) {
        uint32_t kb = sK0 + (j & 1)*ATILE;
        uint32_t vb = sV0 + (j & 1)*ATILE;
        for (int idx = tid; idx < 512; idx += 128) {
            int r = idx >> 3, seg = idx & 7;
            size_t g = hbase + (size_t)(j*64 + r)*64 + seg*8;
            CP16(kb + r*SMSA + seg*16, (const uint4*)(Kh + g));
            CP16(vb + r*SMSA + seg*16, (const uint4*)(Vh + g));
        }
        CP_COMMIT();
    };

    loadKV(0);

    uint32_t qf[4][4];
    float oacc[8][4];
    float m[2] = {-1e30f, -1e30f}, l[2] = {0.f, 0.f};
#pragma unroll
    for (int nt = 0; nt < 8; nt++)
#pragma unroll
        for (int j2 = 0; j2 < 4; j2++) oacc[nt][j2] = 0.f;

    const int rowg = lane >> 2;
    const int colg = (lane & 3) << 1;
    const uint32_t aoff = (warp*16 + (lane & 15))*SMSA + ((lane >> 4) << 4);

    for (int j = 0; j <= qb; j++) {
        if (j < qb) loadKV(j + 1);
        if (j < qb) CP_WAIT1(); else CP_WAIT0();
        __syncthreads();

        if (j == 0) {
#pragma unroll
            for (int kk = 0; kk < 4; kk++)
                LDSM4(qf[kk], sQ + aoff + kk*32);
        }

        const uint32_t kb = sK0 + (j & 1)*ATILE;
        const uint32_t vb = sV0 + (j & 1)*ATILE;

        float sacc[8][4];
#pragma unroll
        for (int nt = 0; nt < 8; nt++)
#pragma unroll
            for (int j2 = 0; j2 < 4; j2++) sacc[nt][j2] = 0.f;

#pragma unroll
        for (int kk = 0; kk < 4; kk++) {
            uint32_t bf[16];
#pragma unroll
            for (int q = 0; q < 4; q++)
                LDSM4(&bf[q*4], kb + (q*16 + (lane & 15))*SMSA
                                  + ((lane >> 4) << 4) + kk*32);
#pragma unroll
            for (int nt = 0; nt < 8; nt++) {
                const int q = (nt >> 1)*4, r = nt & 1;
                MMAH(sacc[nt], qf[kk], bf[q+r], bf[q+2+r]);
            }
        }

        const int grow0 = qb*64 + warp*16 + rowg;
#pragma unroll
        for (int nt = 0; nt < 8; nt++)
#pragma unroll
            for (int j2 = 0; j2 < 4; j2++) {
                float s = sacc[nt][j2] * 0.125f;
                if (j == qb) {
                    int gc = j*64 + nt*8 + colg + (j2 & 1);
                    int gr = grow0 + ((j2 >> 1) << 3);
                    if (gc > gr) s = -1e30f;
                }
                sacc[nt][j2] = s;
            }

        float mt[2] = {-1e30f, -1e30f};
#pragma unroll
        for (int nt = 0; nt < 8; nt++) {
            mt[0] = fmaxf(mt[0], fmaxf(sacc[nt][0], sacc[nt][1]));
            mt[1] = fmaxf(mt[1], fmaxf(sacc[nt][2], sacc[nt][3]));
        }
#pragma unroll
        for (int i = 0; i < 2; i++) {
            mt[i] = fmaxf(mt[i], __shfl_xor_sync(0xFFFFFFFFu, mt[i], 1));
            mt[i] = fmaxf(mt[i], __shfl_xor_sync(0xFFFFFFFFu, mt[i], 2));
        }
        float corr[2], mnew[2];
#pragma unroll
        for (int i = 0; i < 2; i++) {
            mnew[i] = fmaxf(m[i], mt[i]);
            corr[i] = __expf(m[i] - mnew[i]);
            m[i] = mnew[i];
        }
        float ls[2] = {0.f, 0.f};
#pragma unroll
        for (int nt = 0; nt < 8; nt++) {
            sacc[nt][0] = __expf(sacc[nt][0] - mnew[0]);
            sacc[nt][1] = __expf(sacc[nt][1] - mnew[0]);
            sacc[nt][2] = __expf(sacc[nt][2] - mnew[1]);
            sacc[nt][3] = __expf(sacc[nt][3] - mnew[1]);
            ls[0] += sacc[nt][0] + sacc[nt][1];
            ls[1] += sacc[nt][2] + sacc[nt][3];
        }
#pragma unroll
        for (int i = 0; i < 2; i++) {
            ls[i] += __shfl_xor_sync(0xFFFFFFFFu, ls[i], 1);
            ls[i] += __shfl_xor_sync(0xFFFFFFFFu, ls[i], 2);
            l[i] = l[i]*corr[i] + ls[i];
        }
#pragma unroll
        for (int nt = 0; nt < 8; nt++) {
            oacc[nt][0] *= corr[0]; oacc[nt][1] *= corr[0];
            oacc[nt][2] *= corr[1]; oacc[nt][3] *= corr[1];
        }

#pragma unroll
        for (int kt = 0; kt < 4; kt++) {
            uint32_t pa[4];
            pa[0] = f22u(sacc[2*kt  ][0], sacc[2*kt  ][1]);
            pa[1] = f22u(sacc[2*kt  ][2], sacc[2*kt  ][3]);
            pa[2] = f22u(sacc[2*kt+1][0], sacc[2*kt+1][1]);
            pa[3] = f22u(sacc[2*kt+1][2], sacc[2*kt+1][3]);
            uint32_t vf[16];
#pragma unroll
            for (int q = 0; q < 4; q++)
                LDSM4T(&vf[q*4], vb + (kt*16 + (lane & 15))*SMSA
                                    + q*32 + ((lane >> 4) << 4));
#pragma unroll
            for (int nt = 0; nt < 8; nt++) {
                const int base = (nt >> 1)*4 + ((nt & 1) << 1);
                MMAH(oacc[nt], pa, vf[base], vf[base+1]);
            }
        }
        __syncthreads();
    }

    float inv[2] = {1.f / l[0], 1.f / l[1]};
#pragma unroll
    for (int nt = 0; nt < 8; nt++)
#pragma unroll
        for (int j2 = 0; j2 < 4; j2++) {
            int srow = qb*64 + warp*16 + rowg + ((j2 >> 1) << 3);
            int tok = bb*SS + srow;
            int col = hh*64 + nt*8 + colg + (j2 & 1);
            oh[(size_t)tok*DD + col] =
                __float2half_rn(oacc[nt][j2] * inv[j2 >> 1]);
        }
}

// ---------------------------------------------------------------------------
// LayerNorm over D=768, optional fp32 out + fp16 out
// ---------------------------------------------------------------------------
__global__ __launch_bounds__(256) void layernorm_k(const float* __restrict__ X,
                                                   const float* __restrict__ g,
                                                   const float* __restrict__ b,
                                                   float* __restrict__ Y,
                                                   __half* __restrict__ Yh)
{
    int t = blockIdx.x;
    const float* xr = X + (size_t)t * DD;
    float vals[3];
    float s = 0.f, s2 = 0.f;
#pragma unroll
    for (int i = 0; i < 3; i++) {
        float v = xr[threadIdx.x + i * 256];
        vals[i] = v;
        s += v; s2 += v * v;
    }
#pragma unroll
    for (int o = 16; o > 0; o >>= 1) {
        s  += __shfl_xor_sync(0xFFFFFFFFu, s,  o);
        s2 += __shfl_xor_sync(0xFFFFFFFFu, s2, o);
    }
    __shared__ float rs[8], rs2[8];
    int w = threadIdx.x >> 5;
    if ((threadIdx.x & 31) == 0) { rs[w] = s; rs2[w] = s2; }
    __syncthreads();
    if (threadIdx.x < 32) {
        s  = (threadIdx.x < 8) ? rs [threadIdx.x] : 0.f;
        s2 = (threadIdx.x < 8) ? rs2[threadIdx.x] : 0.f;
#pragma unroll
        for (int o = 4; o > 0; o >>= 1) {
            s  += __shfl_xor_sync(0xFFFFFFFFu, s,  o);
            s2 += __shfl_xor_sync(0xFFFFFFFFu, s2, o);
        }
        if (threadIdx.x == 0) { rs[0] = s; rs2[0] = s2; }
    }
    __syncthreads();
    float mean = rs[0] * (1.f / DD);
    float var  = rs2[0] * (1.f / DD) - mean * mean;
    float rstd = rsqrtf(var + 1e-5f);
#pragma unroll
    for (int i = 0; i < 3; i++) {
        int d = threadIdx.x + i * 256;
        float v = (vals[i] - mean) * rstd * g[d] + b[d];
        size_t o = (size_t)t * DD + d;
        if (Y)  Y[o] = v;
        Yh[o] = __float2half_rn(v);
    }
}

// ---------------------------------------------------------------------------
// Launch
// ---------------------------------------------------------------------------
template<int MT>
static inline void run_gemm(const __half* Ah, const __half* Bt,
                            const float* bias, const float* Res,
                            float* C, __half* Ch, __half* K16, __half* V16,
                            int M, int N, int K, int mode)
{
    dim3 grid(M / (32*MT), (N + 127) / 128);
    int smem = 2 * (32*MT*SMS + 128*SMS);
    tgemm_k<MT><<<grid, 256, smem>>>((const uint4*)Ah, (const uint4*)Bt,
                                     bias, Res, C, Ch, K16, V16,
                                     M, N, K, mode);
}

extern "C" void kernel_launch(void* const* d_in, const int* in_sizes, int n_in,
                              void* d_out, int out_size)
{
    const int*   ids    = (const int*)  d_in[0];
    const float* emb    = (const float*)d_in[1];
    const float* W_qkv  = (const float*)d_in[2];
    const float* b_qkv  = (const float*)d_in[3];
    const float* W_o    = (const float*)d_in[4];
    const float* b_o    = (const float*)d_in[5];
    const float* ln1_g  = (const float*)d_in[6];
    const float* ln1_b  = (const float*)d_in[7];
    const float* W_ff1  = (const float*)d_in[8];
    const float* b_ff1  = (const float*)d_in[9];
    const float* W_ff2  = (const float*)d_in[10];
    const float* b_ff2  = (const float*)d_in[11];
    const float* ln2_g  = (const float*)d_in[12];
    const float* ln2_b  = (const float*)d_in[13];
    const float* W_out  = (const float*)d_in[14];
    const float* b_out  = (const float*)d_in[15];
    float* out = (float*)d_out;

    cudaFuncSetAttribute(tgemm_k<4>, cudaFuncAttributeMaxDynamicSharedMemorySize,
                         2*(128*SMS + 128*SMS));
    cudaFuncSetAttribute(tgemm_k<2>, cudaFuncAttributeMaxDynamicSharedMemorySize,
                         2*(64*SMS + 128*SMS));
    cudaFuncSetAttribute(attn_k, cudaFuncAttributeMaxDynamicSharedMemorySize,
                         ASM_TOTAL);

    float *px, *pmha, *ph1, *pffo, *ppb;
    cudaGetSymbolAddress((void**)&px,   g_x);
    cudaGetSymbolAddress((void**)&pmha, g_mha);
    cudaGetSymbolAddress((void**)&ph1,  g_h1);
    cudaGetSymbolAddress((void**)&pffo, g_ffo);
    cudaGetSymbolAddress((void**)&ppb,  g_pebase);

    __half *xh,*ath,*h1h,*ffh,*h2h;
    cudaGetSymbolAddress((void**)&xh,  g_xh);
    cudaGetSymbolAddress((void**)&ath, g_ath);
    cudaGetSymbolAddress((void**)&h1h, g_h1h);
    cudaGetSymbolAddress((void**)&ffh, g_ffh);
    cudaGetSymbolAddress((void**)&h2h, g_h2h);

    __half *qh,*kh,*vh;
    cudaGetSymbolAddress((void**)&qh, g_qh);
    cudaGetSymbolAddress((void**)&kh, g_kh);
    cudaGetSymbolAddress((void**)&vh, g_vh);

    __half *wq,*ws,*w1,*w2,*wo;
    cudaGetSymbolAddress((void**)&wq, g_wqkvT);
    cudaGetSymbolAddress((void**)&ws, g_wsumT);
    cudaGetSymbolAddress((void**)&w1, g_wff1T);
    cudaGetSymbolAddress((void**)&w2, g_wff2T);
    cudaGetSymbolAddress((void**)&wo, g_woutT);

    // Weight prep (K % 64 == 0 for all)
    wconvT_k<<<dim3((3*DD + 63)/64, DD/64), 256>>>(W_qkv, wq, DD, 3*DD);
    wosumT_k<<<dim3(DD/32, DD/32), 256>>>(W_o, ws);
    wconvT_k<<<dim3((FFD + 63)/64, DD/64), 256>>>(W_ff1, w1, DD, FFD);
    wconvT_k<<<dim3((DD + 63)/64, FFD/64), 256>>>(W_ff2, w2, FFD, DD);
    wconvT_k<<<dim3((VV + 63)/64, DD/64), 256>>>(W_out, wo, DD, VV);

    // 1. embeddings + PE
    pebase_k<<<3, 256>>>(ppb);
    embed_k<<<NTOK, 256>>>(ids, emb, ppb, px, xh);

    // 2. QKV projection -> head-major fp16 Q, K, V
    run_gemm<4>(xh, wq, b_qkv, nullptr,
                nullptr, qh, kh, vh,
                NTOK, 3*DD, DD, 1|8);

    // 3. tensor-core flash attention (heavy-first scheduling)
    attn_k<<<dim3(SS/64, HH, BB), 128, ASM_TOTAL>>>(qh, kh, vh, ath);

    // 4. mha = attn @ Wsum + b_o + x  (M64 tiles)
    run_gemm<2>(ath, ws, b_o, px,
                pmha, nullptr, nullptr, nullptr,
                NTOK, DD, DD, 1|4);

    // 5. LN1 (fp32 residual + fp16 out)
    layernorm_k<<<NTOK, 256>>>(pmha, ln1_g, ln1_b, ph1, h1h);

    // 6. FF1 + relu (fp16 out)
    run_gemm<4>(h1h, w1, b_ff1, nullptr,
                nullptr, ffh, nullptr, nullptr,
                NTOK, FFD, DD, 1|2);

    // 7. FF2 + residual (fp32 out; M64 tiles)
    run_gemm<2>(ffh, w2, b_ff2, ph1,
                pffo, nullptr, nullptr, nullptr,
                NTOK, DD, FFD, 1|4);

    // 8. LN2 (fp16 out)
    layernorm_k<<<NTOK, 256>>>(pffo, ln2_g, ln2_b, nullptr, h2h);

    // 9. vocab projection
    run_gemm<4>(h2h, wo, b_out, nullptr,
                out, nullptr, nullptr, nullptr,
                NTOK, VV, DD, 1);
}

// round 12
// speedup vs baseline: 1.2470x; 1.0205x over previous
#include <cuda_runtime.h>
#include <cuda_fp16.h>
#include <math.h>
#include <stdint.h>

// Problem constants
#define BB   2
#define SS   2048
#define DD   768
#define HH   12
#define VV   50257
#define FFD  3072
#define HDIM 64
#define NTOK (BB*SS)

// ---------------------------------------------------------------------------
// Scratch (static device globals -- no allocation allowed)
// ---------------------------------------------------------------------------
__device__ float g_x   [NTOK*DD];      // embeddings + PE (residual for step 4)
__device__ float g_mha [NTOK*DD];
__device__ float g_h1  [NTOK*DD];      // LN1 out fp32 (residual for step 7)
__device__ float g_ffo [NTOK*DD];
__device__ float g_pebase[DD];         // 10000^(-2d/D)

// fp16 activations (A operands, single-term)
__device__ __half g_xh [NTOK*DD];
__device__ __half g_ath[NTOK*DD];
__device__ __half g_h1h[NTOK*DD];
__device__ __half g_ffh[NTOK*FFD];
__device__ __half g_h2h[NTOK*DD];

// head-major attention operands [b][h][s][64]
__device__ __half g_qh[NTOK*DD];
__device__ __half g_kh[NTOK*DD];
__device__ __half g_vh[NTOK*DD];

// fp16 transposed weights [N,K]
__device__ __half g_wqkvT[3*DD*DD];
__device__ __half g_wsumT[DD*DD];
__device__ __half g_wff1T[(size_t)FFD*DD];
__device__ __half g_wff2T[(size_t)DD*FFD];
__device__ __half g_woutT[(size_t)VV*DD];

// ---------------------------------------------------------------------------
// PTX helpers (plain sm_103-safe: cp.async, ldmatrix, mma.sync only)
// ---------------------------------------------------------------------------
__device__ __forceinline__ uint32_t smem_u32(const void* p) {
    uint32_t a;
    asm("{ .reg .u64 t; cvta.to.shared.u64 t, %1; cvt.u32.u64 %0, t; }"
        : "=r"(a) : "l"(p));
    return a;
}

#define CP16(dst, src) \
    asm volatile("cp.async.cg.shared.global [%0], [%1], 16;" \
                 :: "r"(dst), "l"(src) : "memory")
#define CP_COMMIT() asm volatile("cp.async.commit_group;" ::: "memory")
#define CP_WAIT1()  asm volatile("cp.async.wait_group 1;"  ::: "memory")
#define CP_WAIT0()  asm volatile("cp.async.wait_group 0;"  ::: "memory")

#define LDSM4(r, a) \
    asm volatile("ldmatrix.sync.aligned.m8n8.x4.shared.b16 {%0,%1,%2,%3}, [%4];" \
        : "=r"((r)[0]), "=r"((r)[1]), "=r"((r)[2]), "=r"((r)[3]) : "r"(a))

#define LDSM4T(r, a) \
    asm volatile("ldmatrix.sync.aligned.m8n8.x4.trans.shared.b16 {%0,%1,%2,%3}, [%4];" \
        : "=r"((r)[0]), "=r"((r)[1]), "=r"((r)[2]), "=r"((r)[3]) : "r"(a))

#define MMAH(d, a, b0, b1) \
    asm volatile("mma.sync.aligned.m16n8k16.row.col.f32.f16.f16.f32 " \
        "{%0,%1,%2,%3}, {%4,%5,%6,%7}, {%8,%9}, {%0,%1,%2,%3};" \
        : "+f"((d)[0]), "+f"((d)[1]), "+f"((d)[2]), "+f"((d)[3]) \
        : "r"((a)[0]), "r"((a)[1]), "r"((a)[2]), "r"((a)[3]), \
          "r"(b0), "r"(b1))

__device__ __forceinline__ uint32_t f22u(float a, float b) {
    __half2 t = __floats2half2_rn(a, b);
    return *reinterpret_cast<uint32_t*>(&t);
}

// ---------------------------------------------------------------------------
// Single-term fp16 mma.sync GEMM: C[M,N] = A[M,K] @ Bt[N,K]^T
// Template MT = per-warp m-subtiles (4 -> CTA 128xN, 2 -> CTA 64xN).
// 8 warps (2m x 4n), warp tile (16*MT)x32, BK=32, cp.async double-buffer.
// SMEM row stride 80B -> conflict-free ldmatrix (all non-trans LDSM4).
// mode: 1=+bias, 2=relu, 4=+Res, 8=QKV head-major scatter
// ---------------------------------------------------------------------------
#define SMS 80

template<int MT>
__global__ __launch_bounds__(256, 1) void tgemm_k(
    const uint4* __restrict__ Ah, const uint4* __restrict__ Bt,
    const float* __restrict__ bias, const float* __restrict__ Res,
    float* __restrict__ C, __half* __restrict__ Ch,
    __half* __restrict__ K16, __half* __restrict__ V16,
    int M, int N, int K, int mode)
{
    constexpr int ABY = 32*MT*SMS;       // A tile bytes
    constexpr int BUF = ABY + 128*SMS;   // A + B per buffer

    extern __shared__ char sm[];
    const uint32_t sb = smem_u32(sm);
    const int tid  = threadIdx.x;
    const int lane = tid & 31;
    const int warp = tid >> 5;
    const int wm = warp >> 2;
    const int wn = warp & 3;
    const int m0 = blockIdx.x * (32*MT);
    const int n0 = blockIdx.y * 128;

    const int Kv  = K >> 3;
    const int nch = K >> 5;
    const int lrow = tid >> 2;
    const int lseg = tid & 3;

    float acc[MT][4][4];
#pragma unroll
    for (int i = 0; i < MT; i++)
#pragma unroll
        for (int j = 0; j < 4; j++)
#pragma unroll
            for (int k = 0; k < 4; k++) acc[i][j][k] = 0.f;

    auto load_chunk = [&](int c) {
        const int b = c & 1;
        const uint32_t base = sb + b * BUF;
        const int kc4 = c << 2;
#pragma unroll
        for (int it = 0; it < MT/2; it++) {
            int row = lrow + it * 64;
            size_t ga = (size_t)(m0 + row) * Kv + kc4 + lseg;
            CP16(base + row * SMS + lseg * 16, Ah + ga);
        }
#pragma unroll
        for (int it = 0; it < 2; it++) {
            int row = lrow + it * 64;
            int rn = n0 + row; if (rn >= N) rn = N - 1;
            size_t gb = (size_t)rn * Kv + kc4 + lseg;
            CP16(base + ABY + row * SMS + lseg * 16, Bt + gb);
        }
        CP_COMMIT();
    };

    load_chunk(0);

    for (int c = 0; c < nch; c++) {
        if (c + 1 < nch) { load_chunk(c + 1); CP_WAIT1(); }
        else             { CP_WAIT0(); }
        __syncthreads();

        const uint32_t base = sb + (c & 1) * BUF;
        const uint32_t ab = base + (wm * (16*MT) + (lane & 15)) * SMS + ((lane >> 4) << 4);
        const uint32_t bb = base + ABY + (wn * 32 + (lane & 15)) * SMS + ((lane >> 4) << 4);

#pragma unroll
        for (int ks = 0; ks < 2; ks++) {
            const uint32_t ko = ks << 5;
            uint32_t ahf[MT*4], bf[8];
#pragma unroll
            for (int mt = 0; mt < MT; mt++)
                LDSM4(&ahf[mt*4], ab + mt * (16*SMS) + ko);
#pragma unroll
            for (int q = 0; q < 2; q++)
                LDSM4(&bf[q*4], bb + q * (16*SMS) + ko);
#pragma unroll
            for (int mt = 0; mt < MT; mt++)
#pragma unroll
                for (int nt = 0; nt < 4; nt++) {
                    const int q = (nt >> 1) * 4, r = nt & 1;
                    MMAH(acc[mt][nt], &ahf[mt*4], bf[q+r], bf[q+2+r]);
                }
        }
        __syncthreads();
    }

    // epilogue
#pragma unroll
    for (int mt = 0; mt < MT; mt++) {
        const int row0 = m0 + wm * (16*MT) + mt * 16 + (lane >> 2);
#pragma unroll
        for (int nt = 0; nt < 4; nt++) {
            const int col = n0 + wn * 32 + nt * 8 + ((lane & 3) << 1);
            if (col >= N) continue;
            const float* d = acc[mt][nt];
#pragma unroll
            for (int h = 0; h < 2; h++) {
                const int r = row0 + h * 8;
                size_t o = (size_t)r * N + col;
#pragma unroll
                for (int j = 0; j < 2; j++) {
                    if (col + j >= N) break;
                    float x = d[h*2+j];
                    if (mode & 1) x += bias[col+j];
                    if (mode & 4) x += Res[o+j];
                    if (mode & 2) x = fmaxf(x, 0.f);
                    if (mode & 8) {
                        // head-major scatter: [b][head][s][64]
                        int cc = col + j;
                        int bq = r >> 11, sq = r & 2047;
                        int part = cc / DD;          // 0=Q 1=K 2=V
                        int cd = cc - part * DD;
                        int hd = cd >> 6, dd = cd & 63;
                        size_t oo = (((size_t)(bq*HH + hd))*SS + sq)*64 + dd;
                        __half hv = __float2half_rn(x);
                        if (part == 0)      Ch[oo]  = hv;
                        else if (part == 1) K16[oo] = hv;
                        else                V16[oo] = hv;
                    } else {
                        if (C)  C[o+j] = x;
                        if (Ch) Ch[o+j] = __float2half_rn(x);
                    }
                }
            }
        }
    }
}

// ---------------------------------------------------------------------------
// PE frequency table:  pebase[d] = 10000^(-2d/D)
// ---------------------------------------------------------------------------
__global__ void pebase_k(float* __restrict__ pb)
{
    int d = blockIdx.x * 256 + threadIdx.x;
    if (d < DD) pb[d] = powf(10000.0f, -2.0f * (float)d / (float)DD);
}

// ---------------------------------------------------------------------------
// Embedding + positional encoding, fused fp16 convert
// ---------------------------------------------------------------------------
__global__ __launch_bounds__(256) void embed_k(const int* __restrict__ ids,
                                               const float* __restrict__ emb,
                                               const float* __restrict__ pb,
                                               float* __restrict__ x,
                                               __half* __restrict__ xh)
{
    int t = blockIdx.x;
    int s = t % SS;
    int id = ids[t];
    const float* er = emb + (size_t)id * DD;
    size_t base = (size_t)t * DD;
    for (int d = threadIdx.x; d < DD; d += 256) {
        float ang = (float)s * pb[d];
        float pe  = (d & 1) ? cosf(ang) : sinf(ang);
        float v = er[d] + pe;
        x[base + d] = v;
        xh[base + d] = __float2half_rn(v);
    }
}

// ---------------------------------------------------------------------------
// Weight transpose + fp16 convert: W[K,N] -> T[N,K]
// 64(k) x 64(n) tiles, [64][65] conflict-free stage, 16B vector stores.
// ---------------------------------------------------------------------------
__global__ __launch_bounds__(256) void wconvT_k(const float* __restrict__ W,
                                                __half* __restrict__ T,
                                                int K, int N)
{
    __shared__ float t[64][65];
    const int k0 = blockIdx.y * 64, n0 = blockIdx.x * 64;
    const int tid = threadIdx.x;

#pragma unroll
    for (int it = 0; it < 16; it++) {
        int i = tid + it * 256;
        int r = i >> 6, c = i & 63;
        int n = n0 + c;
        t[r][c] = (n < N) ? W[(size_t)(k0 + r) * N + n] : 0.f;
    }
    __syncthreads();

#pragma unroll
    for (int it = 0; it < 2; it++) {
        int i = tid + it * 256;
        int n = i >> 3, kc = (i & 7) << 3;
        if (n0 + n >= N) continue;
        __half h[8];
#pragma unroll
        for (int j = 0; j < 8; j++) h[j] = __float2half_rn(t[kc + j][n]);
        *(uint4*)&T[(size_t)(n0 + n) * K + k0 + kc] = *(uint4*)h;
    }
}

// ---------------------------------------------------------------------------
// W_o head-block sum + transpose + fp16
// ---------------------------------------------------------------------------
__global__ __launch_bounds__(256) void wosumT_k(const float* __restrict__ Wo,
                                                __half* __restrict__ T)
{
    __shared__ float t[32][33];
    int r0 = blockIdx.y * 32, c0 = blockIdx.x * 32;
    int tx = threadIdx.x & 31, ty = threadIdx.x >> 5;
#pragma unroll
    for (int i = 0; i < 4; i++) {
        int r = r0 + ty + i * 8;
        float s = 0.f;
#pragma unroll
        for (int h = 0; h < HH; h++)
            s += Wo[((size_t)(h * DD + r)) * DD + c0 + tx];
        t[ty + i * 8][tx] = s;
    }
    __syncthreads();
#pragma unroll
    for (int i = 0; i < 4; i++) {
        int cc = c0 + ty + i * 8;
        int rr = r0 + tx;
        T[(size_t)cc * DD + rr] = __float2half_rn(t[tx][ty + i * 8]);
    }
}

// ---------------------------------------------------------------------------
// Tensor-core causal flash attention (FA2 style), single-term fp16 Q/K/V/P.
// grid (S/64, H, B), 128 threads (4 warps x 16 Q rows). Heavy tiles first.
// ---------------------------------------------------------------------------
#define SMSA 144
#define ATILE 9216          // 64*144
#define ASM_TOTAL (5*ATILE) // 46080  (Q, K x2, V x2)

__global__ __launch_bounds__(128, 1) void attn_k(
    const __half* __restrict__ Qh,
    const __half* __restrict__ Kh, const __half* __restrict__ Vh,
    __half* __restrict__ oh)
{
    extern __shared__ char sm[];
    const uint32_t sb = smem_u32(sm);
    const int qb = gridDim.x - 1 - blockIdx.x;   // heavy tiles first
    const int hh = blockIdx.y, bb = blockIdx.z;
    const int tid = threadIdx.x, lane = tid & 31, warp = tid >> 5;
    const size_t hbase = ((size_t)(bb*HH + hh)) * SS * 64;

    const uint32_t sQ  = sb;
    const uint32_t sK0 = sb + ATILE;
    const uint32_t sV0 = sb + 3*ATILE;

    for (int idx = tid; idx < 512; idx += 128) {
        int r = idx >> 3, seg = idx & 7;
        size_t g = hbase + (size_t)(qb*64 + r)*64 + seg*8;
        CP16(sQ + r*SMSA + seg*16, (const uint4*)(Qh + g));
    }
    CP_COMMIT();

    auto loadKV = [&](int j) {
        uint32_t kb = sK0 + (j & 1)*ATILE;
        uint32_t vb = sV0 + (j & 1)*ATILE;
        for (int idx = tid; idx < 512; idx += 128) {
            int r = idx >> 3, seg = idx & 7;
            size_t g = hbase + (size_t)(j*64 + r)*64 + seg*8;
            CP16(kb + r*SMSA + seg*16, (const uint4*)(Kh + g));
            CP16(vb + r*SMSA + seg*16, (const uint4*)(Vh + g));
        }
        CP_COMMIT();
    };

    loadKV(0);

    uint32_t qf[4][4];
    float oacc[8][4];
    float m[2] = {-1e30f, -1e30f}, l[2] = {0.f, 0.f};
#pragma unroll
    for (int nt = 0; nt < 8; nt++)
#pragma unroll
        for (int j2 = 0; j2 < 4; j2++) oacc[nt][j2] = 0.f;

    const int rowg = lane >> 2;
    const int colg = (lane & 3) << 1;
    const uint32_t aoff = (warp*16 + (lane & 15))*SMSA + ((lane >> 4) << 4);

    for (int j = 0; j <= qb; j++) {
        if (j < qb) loadKV(j + 1);
        if (j < qb) CP_WAIT1(); else CP_WAIT0();
        __syncthreads();

        if (j == 0) {
#pragma unroll
            for (int kk = 0; kk < 4; kk++)
                LDSM4(qf[kk], sQ + aoff + kk*32);
        }

        const uint32_t kb = sK0 + (j & 1)*ATILE;
        const uint32_t vb = sV0 + (j & 1)*ATILE;

        float sacc[8][4];
#pragma unroll
        for (int nt = 0; nt < 8; nt++)
#pragma unroll
            for (int j2 = 0; j2 < 4; j2++) sacc[nt][j2] = 0.f;

#pragma unroll
        for (int kk = 0; kk < 4; kk++) {
            uint32_t bf[16];
#pragma unroll
            for (int q = 0; q < 4; q++)
                LDSM4(&bf[q*4], kb + (q*16 + (lane & 15))*SMSA
                                  + ((lane >> 4) << 4) + kk*32);
#pragma unroll
            for (int nt = 0; nt < 8; nt++) {
                const int q = (nt >> 1)*4, r = nt & 1;
                MMAH(sacc[nt], qf[kk], bf[q+r], bf[q+2+r]);
            }
        }

        const int grow0 = qb*64 + warp*16 + rowg;
#pragma unroll
        for (int nt = 0; nt < 8; nt++)
#pragma unroll
            for (int j2 = 0; j2 < 4; j2++) {
                float s = sacc[nt][j2] * 0.125f;
                if (j == qb) {
                    int gc = j*64 + nt*8 + colg + (j2 & 1);
                    int gr = grow0 + ((j2 >> 1) << 3);
                    if (gc > gr) s = -1e30f;
                }
                sacc[nt][j2] = s;
            }

        float mt[2] = {-1e30f, -1e30f};
#pragma unroll
        for (int nt = 0; nt < 8; nt++) {
            mt[0] = fmaxf(mt[0], fmaxf(sacc[nt][0], sacc[nt][1]));
            mt[1] = fmaxf(mt[1], fmaxf(sacc[nt][2], sacc[nt][3]));
        }
#pragma unroll
        for (int i = 0; i < 2; i++) {
            mt[i] = fmaxf(mt[i], __shfl_xor_sync(0xFFFFFFFFu, mt[i], 1));
            mt[i] = fmaxf(mt[i], __shfl_xor_sync(0xFFFFFFFFu, mt[i], 2));
        }
        float corr[2], mnew[2];
#pragma unroll
        for (int i = 0; i < 2; i++) {
            mnew[i] = fmaxf(m[i], mt[i]);
            corr[i] = __expf(m[i] - mnew[i]);
            m[i] = mnew[i];
        }
        float ls[2] = {0.f, 0.f};
#pragma unroll
        for (int nt = 0; nt < 8; nt++) {
            sacc[nt][0] = __expf(sacc[nt][0] - mnew[0]);
            sacc[nt][1] = __expf(sacc[nt][1] - mnew[0]);
            sacc[nt][2] = __expf(sacc[nt][2] - mnew[1]);
            sacc[nt][3] = __expf(sacc[nt][3] - mnew[1]);
            ls[0] += sacc[nt][0] + sacc[nt][1];
            ls[1] += sacc[nt][2] + sacc[nt][3];
        }
#pragma unroll
        for (int i = 0; i < 2; i++) {
            ls[i] += __shfl_xor_sync(0xFFFFFFFFu, ls[i], 1);
            ls[i] += __shfl_xor_sync(0xFFFFFFFFu, ls[i], 2);
            l[i] = l[i]*corr[i] + ls[i];
        }
#pragma unroll
        for (int nt = 0; nt < 8; nt++) {
            oacc[nt][0] *= corr[0]; oacc[nt][1] *= corr[0];
            oacc[nt][2] *= corr[1]; oacc[nt][3] *= corr[1];
        }

#pragma unroll
        for (int kt = 0; kt < 4; kt++) {
            uint32_t pa[4];
            pa[0] = f22u(sacc[2*kt  ][0], sacc[2*kt  ][1]);
            pa[1] = f22u(sacc[2*kt  ][2], sacc[2*kt  ][3]);
            pa[2] = f22u(sacc[2*kt+1][0], sacc[2*kt+1][1]);
            pa[3] = f22u(sacc[2*kt+1][2], sacc[2*kt+1][3]);
            uint32_t vf[16];
#pragma unroll
            for (int q = 0; q < 4; q++)
                LDSM4T(&vf[q*4], vb + (kt*16 + (lane & 15))*SMSA
                                    + q*32 + ((lane >> 4) << 4));
#pragma unroll
            for (int nt = 0; nt < 8; nt++) {
                const int base = (nt >> 1)*4 + ((nt & 1) << 1);
                MMAH(oacc[nt], pa, vf[base], vf[base+1]);
            }
        }
        __syncthreads();
    }

    float inv[2] = {1.f / l[0], 1.f / l[1]};
#pragma unroll
    for (int nt = 0; nt < 8; nt++)
#pragma unroll
        for (int j2 = 0; j2 < 4; j2++) {
            int srow = qb*64 + warp*16 + rowg + ((j2 >> 1) << 3);
            int tok = bb*SS + srow;
            int col = hh*64 + nt*8 + colg + (j2 & 1);
            oh[(size_t)tok*DD + col] =
                __float2half_rn(oacc[nt][j2] * inv[j2 >> 1]);
        }
}

// ---------------------------------------------------------------------------
// LayerNorm over D=768, optional fp32 out + fp16 out
// ---------------------------------------------------------------------------
__global__ __launch_bounds__(256) void layernorm_k(const float* __restrict__ X,
                                                   const float* __restrict__ g,
                                                   const float* __restrict__ b,
                                                   float* __restrict__ Y,
                                                   __half* __restrict__ Yh)
{
    int t = blockIdx.x;
    const float* xr = X + (size_t)t * DD;
    float vals[3];
    float s = 0.f, s2 = 0.f;
#pragma unroll
    for (int i = 0; i < 3; i++) {
        float v = xr[threadIdx.x + i * 256];
        vals[i] = v;
        s += v; s2 += v * v;
    }
#pragma unroll
    for (int o = 16; o > 0; o >>= 1) {
        s  += __shfl_xor_sync(0xFFFFFFFFu, s,  o);
        s2 += __shfl_xor_sync(0xFFFFFFFFu, s2, o);
    }
    __shared__ float rs[8], rs2[8];
    int w = threadIdx.x >> 5;
    if ((threadIdx.x & 31) == 0) { rs[w] = s; rs2[w] = s2; }
    __syncthreads();
    if (threadIdx.x < 32) {
        s  = (threadIdx.x < 8) ? rs [threadIdx.x] : 0.f;
        s2 = (threadIdx.x < 8) ? rs2[threadIdx.x] : 0.f;
#pragma unroll
        for (int o = 4; o > 0; o >>= 1) {
            s  += __shfl_xor_sync(0xFFFFFFFFu, s,  o);
            s2 += __shfl_xor_sync(0xFFFFFFFFu, s2, o);
        }
        if (threadIdx.x == 0) { rs[0] = s; rs2[0] = s2; }
    }
    __syncthreads();
    float mean = rs[0] * (1.f / DD);
    float var  = rs2[0] * (1.f / DD) - mean * mean;
    float rstd = rsqrtf(var + 1e-5f);
#pragma unroll
    for (int i = 0; i < 3; i++) {
        int d = threadIdx.x + i * 256;
        float v = (vals[i] - mean) * rstd * g[d] + b[d];
        size_t o = (size_t)t * DD + d;
        if (Y)  Y[o] = v;
        Yh[o] = __float2half_rn(v);
    }
}

// ---------------------------------------------------------------------------
// Launch
// ---------------------------------------------------------------------------
template<int MT>
static inline void run_gemm(const __half* Ah, const __half* Bt,
                            const float* bias, const float* Res,
                            float* C, __half* Ch, __half* K16, __half* V16,
                            int M, int N, int K, int mode)
{
    dim3 grid(M / (32*MT), (N + 127) / 128);
    int smem = 2 * (32*MT*SMS + 128*SMS);
    tgemm_k<MT><<<grid, 256, smem>>>((const uint4*)Ah, (const uint4*)Bt,
                                     bias, Res, C, Ch, K16, V16,
                                     M, N, K, mode);
}

extern "C" void kernel_launch(void* const* d_in, const int* in_sizes, int n_in,
                              void* d_out, int out_size)
{
    const int*   ids    = (const int*)  d_in[0];
    const float* emb    = (const float*)d_in[1];
    const float* W_qkv  = (const float*)d_in[2];
    const float* b_qkv  = (const float*)d_in[3];
    const float* W_o    = (const float*)d_in[4];
    const float* b_o    = (const float*)d_in[5];
    const float* ln1_g  = (const float*)d_in[6];
    const float* ln1_b  = (const float*)d_in[7];
    const float* W_ff1  = (const float*)d_in[8];
    const float* b_ff1  = (const float*)d_in[9];
    const float* W_ff2  = (const float*)d_in[10];
    const float* b_ff2  = (const float*)d_in[11];
    const float* ln2_g  = (const float*)d_in[12];
    const float* ln2_b  = (const float*)d_in[13];
    const float* W_out  = (const float*)d_in[14];
    const float* b_out  = (const float*)d_in[15];
    float* out = (float*)d_out;

    // Lazy one-time stream/event creation (outside graph capture: the
    // harness's first call is the correctness run).
    static cudaStream_t s2 = nullptr;
    static cudaEvent_t evFork, evWq, evWs, evW1, evW2, evWo;
    if (!s2) {
        cudaStreamCreateWithFlags(&s2, cudaStreamNonBlocking);
        cudaEventCreateWithFlags(&evFork, cudaEventDisableTiming);
        cudaEventCreateWithFlags(&evWq,   cudaEventDisableTiming);
        cudaEventCreateWithFlags(&evWs,   cudaEventDisableTiming);
        cudaEventCreateWithFlags(&evW1,   cudaEventDisableTiming);
        cudaEventCreateWithFlags(&evW2,   cudaEventDisableTiming);
        cudaEventCreateWithFlags(&evWo,   cudaEventDisableTiming);
        cudaFuncSetAttribute(tgemm_k<4>, cudaFuncAttributeMaxDynamicSharedMemorySize,
                             2*(128*SMS + 128*SMS));
        cudaFuncSetAttribute(tgemm_k<2>, cudaFuncAttributeMaxDynamicSharedMemorySize,
                             2*(64*SMS + 128*SMS));
        cudaFuncSetAttribute(attn_k, cudaFuncAttributeMaxDynamicSharedMemorySize,
                             ASM_TOTAL);
    }

    float *px, *pmha, *ph1, *pffo, *ppb;
    cudaGetSymbolAddress((void**)&px,   g_x);
    cudaGetSymbolAddress((void**)&pmha, g_mha);
    cudaGetSymbolAddress((void**)&ph1,  g_h1);
    cudaGetSymbolAddress((void**)&pffo, g_ffo);
    cudaGetSymbolAddress((void**)&ppb,  g_pebase);

    __half *xh,*ath,*h1h,*ffh,*h2h;
    cudaGetSymbolAddress((void**)&xh,  g_xh);
    cudaGetSymbolAddress((void**)&ath, g_ath);
    cudaGetSymbolAddress((void**)&h1h, g_h1h);
    cudaGetSymbolAddress((void**)&ffh, g_ffh);
    cudaGetSymbolAddress((void**)&h2h, g_h2h);

    __half *qh,*kh,*vh;
    cudaGetSymbolAddress((void**)&qh, g_qh);
    cudaGetSymbolAddress((void**)&kh, g_kh);
    cudaGetSymbolAddress((void**)&vh, g_vh);

    __half *wq,*ws,*w1,*w2,*wo;
    cudaGetSymbolAddress((void**)&wq, g_wqkvT);
    cudaGetSymbolAddress((void**)&ws, g_wsumT);
    cudaGetSymbolAddress((void**)&w1, g_wff1T);
    cudaGetSymbolAddress((void**)&w2, g_wff2T);
    cudaGetSymbolAddress((void**)&wo, g_woutT);

    // ---- fork: weight prep runs on s2, overlapped with the activation chain
    cudaEventRecord(evFork, 0);
    cudaStreamWaitEvent(s2, evFork, 0);

    wconvT_k<<<dim3((3*DD + 63)/64, DD/64), 256, 0, s2>>>(W_qkv, wq, DD, 3*DD);
    cudaEventRecord(evWq, s2);
    wosumT_k<<<dim3(DD/32, DD/32), 256, 0, s2>>>(W_o, ws);
    cudaEventRecord(evWs, s2);
    wconvT_k<<<dim3((FFD + 63)/64, DD/64), 256, 0, s2>>>(W_ff1, w1, DD, FFD);
    cudaEventRecord(evW1, s2);
    wconvT_k<<<dim3((DD + 63)/64, FFD/64), 256, 0, s2>>>(W_ff2, w2, FFD, DD);
    cudaEventRecord(evW2, s2);
    wconvT_k<<<dim3((VV + 63)/64, DD/64), 256, 0, s2>>>(W_out, wo, DD, VV);
    cudaEventRecord(evWo, s2);

    // ---- main chain (legacy stream)
    // 1. embeddings + PE
    pebase_k<<<3, 256>>>(ppb);
    embed_k<<<NTOK, 256>>>(ids, emb, ppb, px, xh);

    // 2. QKV projection -> head-major fp16 Q, K, V
    cudaStreamWaitEvent(0, evWq, 0);
    run_gemm<4>(xh, wq, b_qkv, nullptr,
                nullptr, qh, kh, vh,
                NTOK, 3*DD, DD, 1|8);

    // 3. tensor-core flash attention (heavy-first scheduling)
    attn_k<<<dim3(SS/64, HH, BB), 128, ASM_TOTAL>>>(qh, kh, vh, ath);

    // 4. mha = attn @ Wsum + b_o + x  (M64 tiles)
    cudaStreamWaitEvent(0, evWs, 0);
    run_gemm<2>(ath, ws, b_o, px,
                pmha, nullptr, nullptr, nullptr,
                NTOK, DD, DD, 1|4);

    // 5. LN1 (fp32 residual + fp16 out)
    layernorm_k<<<NTOK, 256>>>(pmha, ln1_g, ln1_b, ph1, h1h);

    // 6. FF1 + relu (fp16 out)
    cudaStreamWaitEvent(0, evW1, 0);
    run_gemm<4>(h1h, w1, b_ff1, nullptr,
                nullptr, ffh, nullptr, nullptr,
                NTOK, FFD, DD, 1|2);

    // 7. FF2 + residual (fp32 out; M64 tiles)
    cudaStreamWaitEvent(0, evW2, 0);
    run_gemm<2>(ffh, w2, b_ff2, ph1,
                pffo, nullptr, nullptr, nullptr,
                NTOK, DD, FFD, 1|4);

    // 8. LN2 (fp16 out)
    layernorm_k<<<NTOK, 256>>>(pffo, ln2_g, ln2_b, nullptr, h2h);

    // 9. vocab projection (join: W_out convert must be done)
    cudaStreamWaitEvent(0, evWo, 0);
    run_gemm<4>(h2h, wo, b_out, nullptr,
                out, nullptr, nullptr, nullptr,
                NTOK, VV, DD, 1);
}

// round 13
// speedup vs baseline: 1.2687x; 1.0174x over previous
#include <cuda_runtime.h>
#include <cuda_fp16.h>
#include <math.h>
#include <stdint.h>

// Problem constants
#define BB   2
#define SS   2048
#define DD   768
#define HH   12
#define VV   50257
#define FFD  3072
#define HDIM 64
#define NTOK (BB*SS)
#define NQB  (SS/64)        // 32 q-tiles per (b,h)

// ---------------------------------------------------------------------------
// Scratch (static device globals -- no allocation allowed)
// ---------------------------------------------------------------------------
__device__ float g_x   [NTOK*DD];      // embeddings + PE (residual for step 4)
__device__ float g_mha [NTOK*DD];
__device__ float g_h1  [NTOK*DD];      // LN1 out fp32 (residual for step 7)
__device__ float g_ffo [NTOK*DD];
__device__ float g_pebase[DD];         // 10000^(-2d/D)

// fp16 activations (A operands, single-term)
__device__ __half g_xh [NTOK*DD];
__device__ __half g_ath[NTOK*DD];
__device__ __half g_h1h[NTOK*DD];
__device__ __half g_ffh[NTOK*FFD];
__device__ __half g_h2h[NTOK*DD];

// head-major attention operands [b][h][s][64]
__device__ __half g_qh[NTOK*DD];
__device__ __half g_kh[NTOK*DD];
__device__ __half g_vh[NTOK*DD];

// fp16 transposed weights [N,K]
__device__ __half g_wqkvT[3*DD*DD];
__device__ __half g_wsumT[DD*DD];
__device__ __half g_wff1T[(size_t)FFD*DD];
__device__ __half g_wff2T[(size_t)DD*FFD];
__device__ __half g_woutT[(size_t)VV*DD];

// ---------------------------------------------------------------------------
// PTX helpers (plain sm_103-safe: cp.async, ldmatrix, mma.sync only)
// ---------------------------------------------------------------------------
__device__ __forceinline__ uint32_t smem_u32(const void* p) {
    uint32_t a;
    asm("{ .reg .u64 t; cvta.to.shared.u64 t, %1; cvt.u32.u64 %0, t; }"
        : "=r"(a) : "l"(p));
    return a;
}

#define CP16(dst, src) \
    asm volatile("cp.async.cg.shared.global [%0], [%1], 16;" \
                 :: "r"(dst), "l"(src) : "memory")
#define CP_COMMIT() asm volatile("cp.async.commit_group;" ::: "memory")
#define CP_WAIT1()  asm volatile("cp.async.wait_group 1;"  ::: "memory")
#define CP_WAIT0()  asm volatile("cp.async.wait_group 0;"  ::: "memory")

#define LDSM4(r, a) \
    asm volatile("ldmatrix.sync.aligned.m8n8.x4.shared.b16 {%0,%1,%2,%3}, [%4];" \
        : "=r"((r)[0]), "=r"((r)[1]), "=r"((r)[2]), "=r"((r)[3]) : "r"(a))

#define LDSM4T(r, a) \
    asm volatile("ldmatrix.sync.aligned.m8n8.x4.trans.shared.b16 {%0,%1,%2,%3}, [%4];" \
        : "=r"((r)[0]), "=r"((r)[1]), "=r"((r)[2]), "=r"((r)[3]) : "r"(a))

#define MMAH(d, a, b0, b1) \
    asm volatile("mma.sync.aligned.m16n8k16.row.col.f32.f16.f16.f32 " \
        "{%0,%1,%2,%3}, {%4,%5,%6,%7}, {%8,%9}, {%0,%1,%2,%3};" \
        : "+f"((d)[0]), "+f"((d)[1]), "+f"((d)[2]), "+f"((d)[3]) \
        : "r"((a)[0]), "r"((a)[1]), "r"((a)[2]), "r"((a)[3]), \
          "r"(b0), "r"(b1))

__device__ __forceinline__ uint32_t f22u(float a, float b) {
    __half2 t = __floats2half2_rn(a, b);
    return *reinterpret_cast<uint32_t*>(&t);
}

// ---------------------------------------------------------------------------
// Single-term fp16 mma.sync GEMM: C[M,N] = A[M,K] @ Bt[N,K]^T
// Template MT = per-warp m-subtiles (4 -> CTA 128xN, 2 -> CTA 64xN).
// 8 warps (2m x 4n), warp tile (16*MT)x32, BK=32, cp.async double-buffer.
// SMEM row stride 80B -> conflict-free ldmatrix (all non-trans LDSM4).
// mode: 1=+bias, 2=relu, 4=+Res, 8=QKV head-major scatter
// ---------------------------------------------------------------------------
#define SMS 80

template<int MT>
__global__ __launch_bounds__(256, 1) void tgemm_k(
    const uint4* __restrict__ Ah, const uint4* __restrict__ Bt,
    const float* __restrict__ bias, const float* __restrict__ Res,
    float* __restrict__ C, __half* __restrict__ Ch,
    __half* __restrict__ K16, __half* __restrict__ V16,
    int M, int N, int K, int mode)
{
    constexpr int ABY = 32*MT*SMS;       // A tile bytes
    constexpr int BUF = ABY + 128*SMS;   // A + B per buffer

    extern __shared__ char sm[];
    const uint32_t sb = smem_u32(sm);
    const int tid  = threadIdx.x;
    const int lane = tid & 31;
    const int warp = tid >> 5;
    const int wm = warp >> 2;
    const int wn = warp & 3;
    const int m0 = blockIdx.x * (32*MT);
    const int n0 = blockIdx.y * 128;

    const int Kv  = K >> 3;
    const int nch = K >> 5;
    const int lrow = tid >> 2;
    const int lseg = tid & 3;

    float acc[MT][4][4];
#pragma unroll
    for (int i = 0; i < MT; i++)
#pragma unroll
        for (int j = 0; j < 4; j++)
#pragma unroll
            for (int k = 0; k < 4; k++) acc[i][j][k] = 0.f;

    auto load_chunk = [&](int c) {
        const int b = c & 1;
        const uint32_t base = sb + b * BUF;
        const int kc4 = c << 2;
#pragma unroll
        for (int it = 0; it < MT/2; it++) {
            int row = lrow + it * 64;
            size_t ga = (size_t)(m0 + row) * Kv + kc4 + lseg;
            CP16(base + row * SMS + lseg * 16, Ah + ga);
        }
#pragma unroll
        for (int it = 0; it < 2; it++) {
            int row = lrow + it * 64;
            int rn = n0 + row; if (rn >= N) rn = N - 1;
            size_t gb = (size_t)rn * Kv + kc4 + lseg;
            CP16(base + ABY + row * SMS + lseg * 16, Bt + gb);
        }
        CP_COMMIT();
    };

    load_chunk(0);

    for (int c = 0; c < nch; c++) {
        if (c + 1 < nch) { load_chunk(c + 1); CP_WAIT1(); }
        else             { CP_WAIT0(); }
        __syncthreads();

        const uint32_t base = sb + (c & 1) * BUF;
        const uint32_t ab = base + (wm * (16*MT) + (lane & 15)) * SMS + ((lane >> 4) << 4);
        const uint32_t bb = base + ABY + (wn * 32 + (lane & 15)) * SMS + ((lane >> 4) << 4);

#pragma unroll
        for (int ks = 0; ks < 2; ks++) {
            const uint32_t ko = ks << 5;
            uint32_t ahf[MT*4], bf[8];
#pragma unroll
            for (int mt = 0; mt < MT; mt++)
                LDSM4(&ahf[mt*4], ab + mt * (16*SMS) + ko);
#pragma unroll
            for (int q = 0; q < 2; q++)
                LDSM4(&bf[q*4], bb + q * (16*SMS) + ko);
#pragma unroll
            for (int mt = 0; mt < MT; mt++)
#pragma unroll
                for (int nt = 0; nt < 4; nt++) {
                    const int q = (nt >> 1) * 4, r = nt & 1;
                    MMAH(acc[mt][nt], &ahf[mt*4], bf[q+r], bf[q+2+r]);
                }
        }
        __syncthreads();
    }

    // epilogue (vectorized half2 where possible)
#pragma unroll
    for (int mt = 0; mt < MT; mt++) {
        const int row0 = m0 + wm * (16*MT) + mt * 16 + (lane >> 2);
#pragma unroll
        for (int nt = 0; nt < 4; nt++) {
            const int col = n0 + wn * 32 + nt * 8 + ((lane & 3) << 1);
            if (col >= N) continue;
            const bool pair = (col + 1 < N);
            const float* d = acc[mt][nt];
#pragma unroll
            for (int h = 0; h < 2; h++) {
                const int r = row0 + h * 8;
                size_t o = (size_t)r * N + col;
                float v0 = d[h*2+0], v1 = d[h*2+1];
                if (mode & 1) { v0 += bias[col]; if (pair) v1 += bias[col+1]; }
                if (mode & 4) { v0 += Res[o];    if (pair) v1 += Res[o+1]; }
                if (mode & 2) { v0 = fmaxf(v0, 0.f); v1 = fmaxf(v1, 0.f); }
                if (mode & 8) {
                    // head-major scatter: [b][head][s][64]; col even => col,
                    // col+1 stay inside one head (dd even) -> half2 store
                    int bq = r >> 11, sq = r & 2047;
                    int part = col / DD;          // 0=Q 1=K 2=V
                    int cd = col - part * DD;
                    int hd = cd >> 6, dd = cd & 63;
                    size_t oo = (((size_t)(bq*HH + hd))*SS + sq)*64 + dd;
                    __half2 hv = __floats2half2_rn(v0, v1);
                    __half* dst = (part == 0) ? Ch : (part == 1) ? K16 : V16;
                    *(__half2*)(dst + oo) = hv;
                } else {
                    if (C) {
                        C[o] = v0;
                        if (pair) C[o+1] = v1;
                    }
                    if (Ch) {
                        if (pair) *(__half2*)(Ch + o) = __floats2half2_rn(v0, v1);
                        else      Ch[o] = __float2half_rn(v0);
                    }
                }
            }
        }
    }
}

// ---------------------------------------------------------------------------
// PE frequency table:  pebase[d] = 10000^(-2d/D)
// ---------------------------------------------------------------------------
__global__ void pebase_k(float* __restrict__ pb)
{
    int d = blockIdx.x * 256 + threadIdx.x;
    if (d < DD) pb[d] = powf(10000.0f, -2.0f * (float)d / (float)DD);
}

// ---------------------------------------------------------------------------
// Embedding + positional encoding, fused fp16 convert
// ---------------------------------------------------------------------------
__global__ __launch_bounds__(256) void embed_k(const int* __restrict__ ids,
                                               const float* __restrict__ emb,
                                               const float* __restrict__ pb,
                                               float* __restrict__ x,
                                               __half* __restrict__ xh)
{
    int t = blockIdx.x;
    int s = t % SS;
    int id = ids[t];
    const float* er = emb + (size_t)id * DD;
    size_t base = (size_t)t * DD;
    for (int d = threadIdx.x; d < DD; d += 256) {
        float ang = (float)s * pb[d];
        float pe  = (d & 1) ? cosf(ang) : sinf(ang);
        float v = er[d] + pe;
        x[base + d] = v;
        xh[base + d] = __float2half_rn(v);
    }
}

// ---------------------------------------------------------------------------
// Weight transpose + fp16 convert: W[K,N] -> T[N,K]
// 64(k) x 64(n) tiles, [64][65] conflict-free stage, 16B vector stores.
// ---------------------------------------------------------------------------
__global__ __launch_bounds__(256) void wconvT_k(const float* __restrict__ W,
                                                __half* __restrict__ T,
                                                int K, int N)
{
    __shared__ float t[64][65];
    const int k0 = blockIdx.y * 64, n0 = blockIdx.x * 64;
    const int tid = threadIdx.x;

#pragma unroll
    for (int it = 0; it < 16; it++) {
        int i = tid + it * 256;
        int r = i >> 6, c = i & 63;
        int n = n0 + c;
        t[r][c] = (n < N) ? W[(size_t)(k0 + r) * N + n] : 0.f;
    }
    __syncthreads();

#pragma unroll
    for (int it = 0; it < 2; it++) {
        int i = tid + it * 256;
        int n = i >> 3, kc = (i & 7) << 3;
        if (n0 + n >= N) continue;
        __half h[8];
#pragma unroll
        for (int j = 0; j < 8; j++) h[j] = __float2half_rn(t[kc + j][n]);
        *(uint4*)&T[(size_t)(n0 + n) * K + k0 + kc] = *(uint4*)h;
    }
}

// ---------------------------------------------------------------------------
// W_o head-block sum + transpose + fp16
// ---------------------------------------------------------------------------
__global__ __launch_bounds__(256) void wosumT_k(const float* __restrict__ Wo,
                                                __half* __restrict__ T)
{
    __shared__ float t[32][33];
    int r0 = blockIdx.y * 32, c0 = blockIdx.x * 32;
    int tx = threadIdx.x & 31, ty = threadIdx.x >> 5;
#pragma unroll
    for (int i = 0; i < 4; i++) {
        int r = r0 + ty + i * 8;
        float s = 0.f;
#pragma unroll
        for (int h = 0; h < HH; h++)
            s += Wo[((size_t)(h * DD + r)) * DD + c0 + tx];
        t[ty + i * 8][tx] = s;
    }
    __syncthreads();
#pragma unroll
    for (int i = 0; i < 4; i++) {
        int cc = c0 + ty + i * 8;
        int rr = r0 + tx;
        T[(size_t)cc * DD + rr] = __float2half_rn(t[tx][ty + i * 8]);
    }
}

// ---------------------------------------------------------------------------
// Tensor-core causal flash attention (FA2 style), single-term fp16 Q/K/V/P.
// Work-balanced pairing: grid (NQB/2, H, B); CTA cc handles q-tiles
// (NQB-1-cc) then (cc) => exactly NQB+1 KV tiles per CTA (uniform).
// 128 threads (4 warps x 16 Q rows).
// ---------------------------------------------------------------------------
#define SMSA 144
#define ATILE 9216          // 64*144
#define ASM_TOTAL (5*ATILE) // 46080  (Q, K x2, V x2)

__global__ __launch_bounds__(128, 1) void attn_k(
    const __half* __restrict__ Qh,
    const __half* __restrict__ Kh, const __half* __restrict__ Vh,
    __half* __restrict__ oh)
{
    extern __shared__ char sm[];
    const uint32_t sb = smem_u32(sm);
    const int cc = blockIdx.x;                   // 0..NQB/2-1
    const int hh = blockIdx.y, bb = blockIdx.z;
    const int tid = threadIdx.x, lane = tid & 31, warp = tid >> 5;
    const size_t hbase = ((size_t)(bb*HH + hh)) * SS * 64;

    const uint32_t sQ  = sb;
    const uint32_t sK0 = sb + ATILE;
    const uint32_t sV0 = sb + 3*ATILE;

    const int rowg = lane >> 2;
    const int colg = (lane & 3) << 1;
    const uint32_t aoff = (warp*16 + (lane & 15))*SMSA + ((lane >> 4) << 4);

#pragma unroll 1
    for (int half = 0; half < 2; half++) {
        const int qb = half ? cc : (NQB - 1 - cc);

        // Q tile
        for (int idx = tid; idx < 512; idx += 128) {
            int r = idx >> 3, seg = idx & 7;
            size_t g = hbase + (size_t)(qb*64 + r)*64 + seg*8;
            CP16(sQ + r*SMSA + seg*16, (const uint4*)(Qh + g));
        }
        CP_COMMIT();

        auto loadKV = [&](int j) {
            uint32_t kb = sK0 + (j & 1)*ATILE;
            uint32_t vb = sV0 + (j & 1)*ATILE;
            for (int idx = tid; idx < 512; idx += 128) {
                int r = idx >> 3, seg = idx & 7;
                size_t g = hbase + (size_t)(j*64 + r)*64 + seg*8;
                CP16(kb + r*SMSA + seg*16, (const uint4*)(Kh + g));
                CP16(vb + r*SMSA + seg*16, (const uint4*)(Vh + g));
            }
            CP_COMMIT();
        };

        loadKV(0);

        uint32_t qf[4][4];
        float oacc[8][4];
        float m[2] = {-1e30f, -1e30f}, l[2] = {0.f, 0.f};
#pragma unroll
        for (int nt = 0; nt < 8; nt++)
#pragma unroll
            for (int j2 = 0; j2 < 4; j2++) oacc[nt][j2] = 0.f;

        for (int j = 0; j <= qb; j++) {
            if (j < qb) loadKV(j + 1);
            if (j < qb) CP_WAIT1(); else CP_WAIT0();
            __syncthreads();

            if (j == 0) {
#pragma unroll
                for (int kk = 0; kk < 4; kk++)
                    LDSM4(qf[kk], sQ + aoff + kk*32);
            }

            const uint32_t kb = sK0 + (j & 1)*ATILE;
            const uint32_t vb = sV0 + (j & 1)*ATILE;

            float sacc[8][4];
#pragma unroll
            for (int nt = 0; nt < 8; nt++)
#pragma unroll
                for (int j2 = 0; j2 < 4; j2++) sacc[nt][j2] = 0.f;

#pragma unroll
            for (int kk = 0; kk < 4; kk++) {
                uint32_t bf[16];
#pragma unroll
                for (int q = 0; q < 4; q++)
                    LDSM4(&bf[q*4], kb + (q*16 + (lane & 15))*SMSA
                                      + ((lane >> 4) << 4) + kk*32);
#pragma unroll
                for (int nt = 0; nt < 8; nt++) {
                    const int q = (nt >> 1)*4, r = nt & 1;
                    MMAH(sacc[nt], qf[kk], bf[q+r], bf[q+2+r]);
                }
            }

            const int grow0 = qb*64 + warp*16 + rowg;
#pragma unroll
            for (int nt = 0; nt < 8; nt++)
#pragma unroll
                for (int j2 = 0; j2 < 4; j2++) {
                    float s = sacc[nt][j2] * 0.125f;
                    if (j == qb) {
                        int gc = j*64 + nt*8 + colg + (j2 & 1);
                        int gr = grow0 + ((j2 >> 1) << 3);
                        if (gc > gr) s = -1e30f;
                    }
                    sacc[nt][j2] = s;
                }

            float mt[2] = {-1e30f, -1e30f};
#pragma unroll
            for (int nt = 0; nt < 8; nt++) {
                mt[0] = fmaxf(mt[0], fmaxf(sacc[nt][0], sacc[nt][1]));
                mt[1] = fmaxf(mt[1], fmaxf(sacc[nt][2], sacc[nt][3]));
            }
#pragma unroll
            for (int i = 0; i < 2; i++) {
                mt[i] = fmaxf(mt[i], __shfl_xor_sync(0xFFFFFFFFu, mt[i], 1));
                mt[i] = fmaxf(mt[i], __shfl_xor_sync(0xFFFFFFFFu, mt[i], 2));
            }
            float corr[2], mnew[2];
#pragma unroll
            for (int i = 0; i < 2; i++) {
                mnew[i] = fmaxf(m[i], mt[i]);
                corr[i] = __expf(m[i] - mnew[i]);
                m[i] = mnew[i];
            }
            float ls[2] = {0.f, 0.f};
#pragma unroll
            for (int nt = 0; nt < 8; nt++) {
                sacc[nt][0] = __expf(sacc[nt][0] - mnew[0]);
                sacc[nt][1] = __expf(sacc[nt][1] - mnew[0]);
                sacc[nt][2] = __expf(sacc[nt][2] - mnew[1]);
                sacc[nt][3] = __expf(sacc[nt][3] - mnew[1]);
                ls[0] += sacc[nt][0] + sacc[nt][1];
                ls[1] += sacc[nt][2] + sacc[nt][3];
            }
#pragma unroll
            for (int i = 0; i < 2; i++) {
                ls[i] += __shfl_xor_sync(0xFFFFFFFFu, ls[i], 1);
                ls[i] += __shfl_xor_sync(0xFFFFFFFFu, ls[i], 2);
                l[i] = l[i]*corr[i] + ls[i];
            }
#pragma unroll
            for (int nt = 0; nt < 8; nt++) {
                oacc[nt][0] *= corr[0]; oacc[nt][1] *= corr[0];
                oacc[nt][2] *= corr[1]; oacc[nt][3] *= corr[1];
            }

#pragma unroll
            for (int kt = 0; kt < 4; kt++) {
                uint32_t pa[4];
                pa[0] = f22u(sacc[2*kt  ][0], sacc[2*kt  ][1]);
                pa[1] = f22u(sacc[2*kt  ][2], sacc[2*kt  ][3]);
                pa[2] = f22u(sacc[2*kt+1][0], sacc[2*kt+1][1]);
                pa[3] = f22u(sacc[2*kt+1][2], sacc[2*kt+1][3]);
                uint32_t vf[16];
#pragma unroll
                for (int q = 0; q < 4; q++)
                    LDSM4T(&vf[q*4], vb + (kt*16 + (lane & 15))*SMSA
                                        + q*32 + ((lane >> 4) << 4));
#pragma unroll
                for (int nt = 0; nt < 8; nt++) {
                    const int base = (nt >> 1)*4 + ((nt & 1) << 1);
                    MMAH(oacc[nt], pa, vf[base], vf[base+1]);
                }
            }
            __syncthreads();
        }

        float inv[2] = {1.f / l[0], 1.f / l[1]};
#pragma unroll
        for (int nt = 0; nt < 8; nt++) {
            int srow0 = qb*64 + warp*16 + rowg;
            int col = hh*64 + nt*8 + colg;        // even -> half2 aligned
#pragma unroll
            for (int hr = 0; hr < 2; hr++) {
                int tok = bb*SS + srow0 + hr*8;
                __half2 hv = __floats2half2_rn(oacc[nt][hr*2] * inv[hr],
                                               oacc[nt][hr*2+1] * inv[hr]);
                *(__half2*)(oh + (size_t)tok*DD + col) = hv;
            }
        }
    }
}

// ---------------------------------------------------------------------------
// LayerNorm over D=768, optional fp32 out + fp16 out
// ---------------------------------------------------------------------------
__global__ __launch_bounds__(256) void layernorm_k(const float* __restrict__ X,
                                                   const float* __restrict__ g,
                                                   const float* __restrict__ b,
                                                   float* __restrict__ Y,
                                                   __half* __restrict__ Yh)
{
    int t = blockIdx.x;
    const float* xr = X + (size_t)t * DD;
    float vals[3];
    float s = 0.f, s2 = 0.f;
#pragma unroll
    for (int i = 0; i < 3; i++) {
        float v = xr[threadIdx.x + i * 256];
        vals[i] = v;
        s += v; s2 += v * v;
    }
#pragma unroll
    for (int o = 16; o > 0; o >>= 1) {
        s  += __shfl_xor_sync(0xFFFFFFFFu, s,  o);
        s2 += __shfl_xor_sync(0xFFFFFFFFu, s2, o);
    }
    __shared__ float rs[8], rs2[8];
    int w = threadIdx.x >> 5;
    if ((threadIdx.x & 31) == 0) { rs[w] = s; rs2[w] = s2; }
    __syncthreads();
    if (threadIdx.x < 32) {
        s  = (threadIdx.x < 8) ? rs [threadIdx.x] : 0.f;
        s2 = (threadIdx.x < 8) ? rs2[threadIdx.x] : 0.f;
#pragma unroll
        for (int o = 4; o > 0; o >>= 1) {
            s  += __shfl_xor_sync(0xFFFFFFFFu, s,  o);
            s2 += __shfl_xor_sync(0xFFFFFFFFu, s2, o);
        }
        if (threadIdx.x == 0) { rs[0] = s; rs2[0] = s2; }
    }
    __syncthreads();
    float mean = rs[0] * (1.f / DD);
    float var  = rs2[0] * (1.f / DD) - mean * mean;
    float rstd = rsqrtf(var + 1e-5f);
#pragma unroll
    for (int i = 0; i < 3; i++) {
        int d = threadIdx.x + i * 256;
        float v = (vals[i] - mean) * rstd * g[d] + b[d];
        size_t o = (size_t)t * DD + d;
        if (Y)  Y[o] = v;
        Yh[o] = __float2half_rn(v);
    }
}

// ---------------------------------------------------------------------------
// Launch
// ---------------------------------------------------------------------------
template<int MT>
static inline void run_gemm(const __half* Ah, const __half* Bt,
                            const float* bias, const float* Res,
                            float* C, __half* Ch, __half* K16, __half* V16,
                            int M, int N, int K, int mode)
{
    dim3 grid(M / (32*MT), (N + 127) / 128);
    int smem = 2 * (32*MT*SMS + 128*SMS);
    tgemm_k<MT><<<grid, 256, smem>>>((const uint4*)Ah, (const uint4*)Bt,
                                     bias, Res, C, Ch, K16, V16,
                                     M, N, K, mode);
}

extern "C" void kernel_launch(void* const* d_in, const int* in_sizes, int n_in,
                              void* d_out, int out_size)
{
    const int*   ids    = (const int*)  d_in[0];
    const float* emb    = (const float*)d_in[1];
    const float* W_qkv  = (const float*)d_in[2];
    const float* b_qkv  = (const float*)d_in[3];
    const float* W_o    = (const float*)d_in[4];
    const float* b_o    = (const float*)d_in[5];
    const float* ln1_g  = (const float*)d_in[6];
    const float* ln1_b  = (const float*)d_in[7];
    const float* W_ff1  = (const float*)d_in[8];
    const float* b_ff1  = (const float*)d_in[9];
    const float* W_ff2  = (const float*)d_in[10];
    const float* b_ff2  = (const float*)d_in[11];
    const float* ln2_g  = (const float*)d_in[12];
    const float* ln2_b  = (const float*)d_in[13];
    const float* W_out  = (const float*)d_in[14];
    const float* b_out  = (const float*)d_in[15];
    float* out = (float*)d_out;

    // Lazy one-time stream/event creation (outside graph capture: the
    // harness's first call is the correctness run).
    static cudaStream_t s2 = nullptr;
    static cudaEvent_t evFork, evWq, evWs, evW1, evW2, evWo;
    if (!s2) {
        cudaStreamCreateWithFlags(&s2, cudaStreamNonBlocking);
        cudaEventCreateWithFlags(&evFork, cudaEventDisableTiming);
        cudaEventCreateWithFlags(&evWq,   cudaEventDisableTiming);
        cudaEventCreateWithFlags(&evWs,   cudaEventDisableTiming);
        cudaEventCreateWithFlags(&evW1,   cudaEventDisableTiming);
        cudaEventCreateWithFlags(&evW2,   cudaEventDisableTiming);
        cudaEventCreateWithFlags(&evWo,   cudaEventDisableTiming);
        cudaFuncSetAttribute(tgemm_k<4>, cudaFuncAttributeMaxDynamicSharedMemorySize,
                             2*(128*SMS + 128*SMS));
        cudaFuncSetAttribute(tgemm_k<2>, cudaFuncAttributeMaxDynamicSharedMemorySize,
                             2*(64*SMS + 128*SMS));
        cudaFuncSetAttribute(attn_k, cudaFuncAttributeMaxDynamicSharedMemorySize,
                             ASM_TOTAL);
    }

    float *px, *pmha, *ph1, *pffo, *ppb;
    cudaGetSymbolAddress((void**)&px,   g_x);
    cudaGetSymbolAddress((void**)&pmha, g_mha);
    cudaGetSymbolAddress((void**)&ph1,  g_h1);
    cudaGetSymbolAddress((void**)&pffo, g_ffo);
    cudaGetSymbolAddress((void**)&ppb,  g_pebase);

    __half *xh,*ath,*h1h,*ffh,*h2h;
    cudaGetSymbolAddress((void**)&xh,  g_xh);
    cudaGetSymbolAddress((void**)&ath, g_ath);
    cudaGetSymbolAddress((void**)&h1h, g_h1h);
    cudaGetSymbolAddress((void**)&ffh, g_ffh);
    cudaGetSymbolAddress((void**)&h2h, g_h2h);

    __half *qh,*kh,*vh;
    cudaGetSymbolAddress((void**)&qh, g_qh);
    cudaGetSymbolAddress((void**)&kh, g_kh);
    cudaGetSymbolAddress((void**)&vh, g_vh);

    __half *wq,*ws,*w1,*w2,*wo;
    cudaGetSymbolAddress((void**)&wq, g_wqkvT);
    cudaGetSymbolAddress((void**)&ws, g_wsumT);
    cudaGetSymbolAddress((void**)&w1, g_wff1T);
    cudaGetSymbolAddress((void**)&w2, g_wff2T);
    cudaGetSymbolAddress((void**)&wo, g_woutT);

    // ---- fork: weight prep runs on s2, overlapped with the activation chain
    cudaEventRecord(evFork, 0);
    cudaStreamWaitEvent(s2, evFork, 0);

    wconvT_k<<<dim3((3*DD + 63)/64, DD/64), 256, 0, s2>>>(W_qkv, wq, DD, 3*DD);
    cudaEventRecord(evWq, s2);
    wosumT_k<<<dim3(DD/32, DD/32), 256, 0, s2>>>(W_o, ws);
    cudaEventRecord(evWs, s2);
    wconvT_k<<<dim3((FFD + 63)/64, DD/64), 256, 0, s2>>>(W_ff1, w1, DD, FFD);
    cudaEventRecord(evW1, s2);
    wconvT_k<<<dim3((DD + 63)/64, FFD/64), 256, 0, s2>>>(W_ff2, w2, FFD, DD);
    cudaEventRecord(evW2, s2);
    wconvT_k<<<dim3((VV + 63)/64, DD/64), 256, 0, s2>>>(W_out, wo, DD, VV);
    cudaEventRecord(evWo, s2);

    // ---- main chain (legacy stream)
    // 1. embeddings + PE
    pebase_k<<<3, 256>>>(ppb);
    embed_k<<<NTOK, 256>>>(ids, emb, ppb, px, xh);

    // 2. QKV projection -> head-major fp16 Q, K, V
    cudaStreamWaitEvent(0, evWq, 0);
    run_gemm<4>(xh, wq, b_qkv, nullptr,
                nullptr, qh, kh, vh,
                NTOK, 3*DD, DD, 1|8);

    // 3. tensor-core flash attention (work-balanced paired tiles)
    attn_k<<<dim3(NQB/2, HH, BB), 128, ASM_TOTAL>>>(qh, kh, vh, ath);

    // 4. mha = attn @ Wsum + b_o + x  (M64 tiles)
    cudaStreamWaitEvent(0, evWs, 0);
    run_gemm<2>(ath, ws, b_o, px,
                pmha, nullptr, nullptr, nullptr,
                NTOK, DD, DD, 1|4);

    // 5. LN1 (fp32 residual + fp16 out)
    layernorm_k<<<NTOK, 256>>>(pmha, ln1_g, ln1_b, ph1, h1h);

    // 6. FF1 + relu (fp16 out)
    cudaStreamWaitEvent(0, evW1, 0);
    run_gemm<4>(h1h, w1, b_ff1, nullptr,
                nullptr, ffh, nullptr, nullptr,
                NTOK, FFD, DD, 1|2);

    // 7. FF2 + residual (fp32 out; M64 tiles)
    cudaStreamWaitEvent(0, evW2, 0);
    run_gemm<2>(ffh, w2, b_ff2, ph1,
                pffo, nullptr, nullptr, nullptr,
                NTOK, DD, FFD, 1|4);

    // 8. LN2 (fp16 out)
    layernorm_k<<<NTOK, 256>>>(pffo, ln2_g, ln2_b, nullptr, h2h);

    // 9. vocab projection (join: W_out convert must be done)
    cudaStreamWaitEvent(0, evWo, 0);
    run_gemm<4>(h2h, wo, b_out, nullptr,
                out, nullptr, nullptr, nullptr,
                NTOK, VV, DD, 1);
}

// round 14
// speedup vs baseline: 1.2697x; 1.0008x over previous
#include <cuda_runtime.h>
#include <cuda_fp16.h>
#include <math.h>
#include <stdint.h>

// Problem constants
#define BB   2
#define SS   2048
#define DD   768
#define HH   12
#define VV   50257
#define FFD  3072
#define HDIM 64
#define NTOK (BB*SS)
#define NQB  (SS/64)        // 32 q-tiles per (b,h)

// ---------------------------------------------------------------------------
// Scratch (static device globals -- no allocation allowed)
// ---------------------------------------------------------------------------
__device__ float g_x   [NTOK*DD];      // embeddings + PE (residual for step 4)
__device__ float g_mha [NTOK*DD];
__device__ float g_h1  [NTOK*DD];      // LN1 out fp32 (residual for step 7)
__device__ float g_ffo [NTOK*DD];
__device__ float g_pebase[DD];         // 10000^(-2d/D)

// fp16 activations (A operands, single-term)
__device__ __half g_xh [NTOK*DD];
__device__ __half g_ath[NTOK*DD];
__device__ __half g_h1h[NTOK*DD];
__device__ __half g_ffh[NTOK*FFD];
__device__ __half g_h2h[NTOK*DD];

// head-major attention operands [b][h][s][64]
__device__ __half g_qh[NTOK*DD];
__device__ __half g_kh[NTOK*DD];
__device__ __half g_vh[NTOK*DD];

// fp16 transposed weights [N,K]
__device__ __half g_wqkvT[3*DD*DD];
__device__ __half g_wsumT[DD*DD];
__device__ __half g_wff1T[(size_t)FFD*DD];
__device__ __half g_wff2T[(size_t)DD*FFD];
__device__ __half g_woutT[(size_t)VV*DD];

// ---------------------------------------------------------------------------
// PTX helpers (plain sm_103-safe: cp.async, ldmatrix, mma.sync only)
// ---------------------------------------------------------------------------
__device__ __forceinline__ uint32_t smem_u32(const void* p) {
    uint32_t a;
    asm("{ .reg .u64 t; cvta.to.shared.u64 t, %1; cvt.u32.u64 %0, t; }"
        : "=r"(a) : "l"(p));
    return a;
}

#define CP16(dst, src) \
    asm volatile("cp.async.cg.shared.global [%0], [%1], 16;" \
                 :: "r"(dst), "l"(src) : "memory")
#define CP_COMMIT() asm volatile("cp.async.commit_group;" ::: "memory")
#define CP_WAIT1()  asm volatile("cp.async.wait_group 1;"  ::: "memory")
#define CP_WAIT0()  asm volatile("cp.async.wait_group 0;"  ::: "memory")

#define LDSM4(r, a) \
    asm volatile("ldmatrix.sync.aligned.m8n8.x4.shared.b16 {%0,%1,%2,%3}, [%4];" \
        : "=r"((r)[0]), "=r"((r)[1]), "=r"((r)[2]), "=r"((r)[3]) : "r"(a))

#define LDSM4T(r, a) \
    asm volatile("ldmatrix.sync.aligned.m8n8.x4.trans.shared.b16 {%0,%1,%2,%3}, [%4];" \
        : "=r"((r)[0]), "=r"((r)[1]), "=r"((r)[2]), "=r"((r)[3]) : "r"(a))

#define MMAH(d, a, b0, b1) \
    asm volatile("mma.sync.aligned.m16n8k16.row.col.f32.f16.f16.f32 " \
        "{%0,%1,%2,%3}, {%4,%5,%6,%7}, {%8,%9}, {%0,%1,%2,%3};" \
        : "+f"((d)[0]), "+f"((d)[1]), "+f"((d)[2]), "+f"((d)[3]) \
        : "r"((a)[0]), "r"((a)[1]), "r"((a)[2]), "r"((a)[3]), \
          "r"(b0), "r"(b1))

__device__ __forceinline__ uint32_t f22u(float a, float b) {
    __half2 t = __floats2half2_rn(a, b);
    return *reinterpret_cast<uint32_t*>(&t);
}

// ---------------------------------------------------------------------------
// Single-term fp16 mma.sync GEMM: C[M,N] = A[M,K] @ Bt[N,K]^T
// Template MT = per-warp m-subtiles (4 -> CTA 128xN, 2 -> CTA 64xN).
// 8 warps (2m x 4n), warp tile (16*MT)x32, BK=32, cp.async double-buffer.
// 2 CTAs/SM (launch_bounds minBlocks=2) to overlap prologue/epilogue
// across co-resident CTAs.
// mode: 1=+bias, 2=relu, 4=+Res, 8=QKV head-major scatter
// ---------------------------------------------------------------------------
#define SMS 80

template<int MT>
__global__ __launch_bounds__(256, 2) void tgemm_k(
    const uint4* __restrict__ Ah, const uint4* __restrict__ Bt,
    const float* __restrict__ bias, const float* __restrict__ Res,
    float* __restrict__ C, __half* __restrict__ Ch,
    __half* __restrict__ K16, __half* __restrict__ V16,
    int M, int N, int K, int mode)
{
    constexpr int ABY = 32*MT*SMS;       // A tile bytes
    constexpr int BUF = ABY + 128*SMS;   // A + B per buffer

    extern __shared__ char sm[];
    const uint32_t sb = smem_u32(sm);
    const int tid  = threadIdx.x;
    const int lane = tid & 31;
    const int warp = tid >> 5;
    const int wm = warp >> 2;
    const int wn = warp & 3;
    const int m0 = blockIdx.x * (32*MT);
    const int n0 = blockIdx.y * 128;

    const int Kv  = K >> 3;
    const int nch = K >> 5;
    const int lrow = tid >> 2;
    const int lseg = tid & 3;

    float acc[MT][4][4];
#pragma unroll
    for (int i = 0; i < MT; i++)
#pragma unroll
        for (int j = 0; j < 4; j++)
#pragma unroll
            for (int k = 0; k < 4; k++) acc[i][j][k] = 0.f;

    auto load_chunk = [&](int c) {
        const int b = c & 1;
        const uint32_t base = sb + b * BUF;
        const int kc4 = c << 2;
#pragma unroll
        for (int it = 0; it < MT/2; it++) {
            int row = lrow + it * 64;
            size_t ga = (size_t)(m0 + row) * Kv + kc4 + lseg;
            CP16(base + row * SMS + lseg * 16, Ah + ga);
        }
#pragma unroll
        for (int it = 0; it < 2; it++) {
            int row = lrow + it * 64;
            int rn = n0 + row; if (rn >= N) rn = N - 1;
            size_t gb = (size_t)rn * Kv + kc4 + lseg;
            CP16(base + ABY + row * SMS + lseg * 16, Bt + gb);
        }
        CP_COMMIT();
    };

    load_chunk(0);

    for (int c = 0; c < nch; c++) {
        if (c + 1 < nch) { load_chunk(c + 1); CP_WAIT1(); }
        else             { CP_WAIT0(); }
        __syncthreads();

        const uint32_t base = sb + (c & 1) * BUF;
        const uint32_t ab = base + (wm * (16*MT) + (lane & 15)) * SMS + ((lane >> 4) << 4);
        const uint32_t bb = base + ABY + (wn * 32 + (lane & 15)) * SMS + ((lane >> 4) << 4);

#pragma unroll
        for (int ks = 0; ks < 2; ks++) {
            const uint32_t ko = ks << 5;
            uint32_t ahf[MT*4], bf[8];
#pragma unroll
            for (int mt = 0; mt < MT; mt++)
                LDSM4(&ahf[mt*4], ab + mt * (16*SMS) + ko);
#pragma unroll
            for (int q = 0; q < 2; q++)
                LDSM4(&bf[q*4], bb + q * (16*SMS) + ko);
#pragma unroll
            for (int mt = 0; mt < MT; mt++)
#pragma unroll
                for (int nt = 0; nt < 4; nt++) {
                    const int q = (nt >> 1) * 4, r = nt & 1;
                    MMAH(acc[mt][nt], &ahf[mt*4], bf[q+r], bf[q+2+r]);
                }
        }
        __syncthreads();
    }

    // epilogue (vectorized half2 where possible)
#pragma unroll
    for (int mt = 0; mt < MT; mt++) {
        const int row0 = m0 + wm * (16*MT) + mt * 16 + (lane >> 2);
#pragma unroll
        for (int nt = 0; nt < 4; nt++) {
            const int col = n0 + wn * 32 + nt * 8 + ((lane & 3) << 1);
            if (col >= N) continue;
            const bool pair = (col + 1 < N);
            const float* d = acc[mt][nt];
#pragma unroll
            for (int h = 0; h < 2; h++) {
                const int r = row0 + h * 8;
                size_t o = (size_t)r * N + col;
                float v0 = d[h*2+0], v1 = d[h*2+1];
                if (mode & 1) { v0 += bias[col]; if (pair) v1 += bias[col+1]; }
                if (mode & 4) { v0 += Res[o];    if (pair) v1 += Res[o+1]; }
                if (mode & 2) { v0 = fmaxf(v0, 0.f); v1 = fmaxf(v1, 0.f); }
                if (mode & 8) {
                    // head-major scatter: [b][head][s][64]; col even => col,
                    // col+1 stay inside one head (dd even) -> half2 store
                    int bq = r >> 11, sq = r & 2047;
                    int part = col / DD;          // 0=Q 1=K 2=V
                    int cd = col - part * DD;
                    int hd = cd >> 6, dd = cd & 63;
                    size_t oo = (((size_t)(bq*HH + hd))*SS + sq)*64 + dd;
                    __half2 hv = __floats2half2_rn(v0, v1);
                    __half* dst = (part == 0) ? Ch : (part == 1) ? K16 : V16;
                    *(__half2*)(dst + oo) = hv;
                } else {
                    if (C) {
                        C[o] = v0;
                        if (pair) C[o+1] = v1;
                    }
                    if (Ch) {
                        if (pair) *(__half2*)(Ch + o) = __floats2half2_rn(v0, v1);
                        else      Ch[o] = __float2half_rn(v0);
                    }
                }
            }
        }
    }
}

// ---------------------------------------------------------------------------
// PE frequency table:  pebase[d] = 10000^(-2d/D)
// ---------------------------------------------------------------------------
__global__ void pebase_k(float* __restrict__ pb)
{
    int d = blockIdx.x * 256 + threadIdx.x;
    if (d < DD) pb[d] = powf(10000.0f, -2.0f * (float)d / (float)DD);
}

// ---------------------------------------------------------------------------
// Embedding + positional encoding, fused fp16 convert
// ---------------------------------------------------------------------------
__global__ __launch_bounds__(256) void embed_k(const int* __restrict__ ids,
                                               const float* __restrict__ emb,
                                               const float* __restrict__ pb,
                                               float* __restrict__ x,
                                               __half* __restrict__ xh)
{
    int t = blockIdx.x;
    int s = t % SS;
    int id = ids[t];
    const float* er = emb + (size_t)id * DD;
    size_t base = (size_t)t * DD;
    for (int d = threadIdx.x; d < DD; d += 256) {
        float ang = (float)s * pb[d];
        float pe  = (d & 1) ? cosf(ang) : sinf(ang);
        float v = er[d] + pe;
        x[base + d] = v;
        xh[base + d] = __float2half_rn(v);
    }
}

// ---------------------------------------------------------------------------
// Weight transpose + fp16 convert: W[K,N] -> T[N,K]
// 64(k) x 64(n) tiles, [64][65] conflict-free stage, 16B vector stores.
// ---------------------------------------------------------------------------
__global__ __launch_bounds__(256) void wconvT_k(const float* __restrict__ W,
                                                __half* __restrict__ T,
                                                int K, int N)
{
    __shared__ float t[64][65];
    const int k0 = blockIdx.y * 64, n0 = blockIdx.x * 64;
    const int tid = threadIdx.x;

#pragma unroll
    for (int it = 0; it < 16; it++) {
        int i = tid + it * 256;
        int r = i >> 6, c = i & 63;
        int n = n0 + c;
        t[r][c] = (n < N) ? W[(size_t)(k0 + r) * N + n] : 0.f;
    }
    __syncthreads();

#pragma unroll
    for (int it = 0; it < 2; it++) {
        int i = tid + it * 256;
        int n = i >> 3, kc = (i & 7) << 3;
        if (n0 + n >= N) continue;
        __half h[8];
#pragma unroll
        for (int j = 0; j < 8; j++) h[j] = __float2half_rn(t[kc + j][n]);
        *(uint4*)&T[(size_t)(n0 + n) * K + k0 + kc] = *(uint4*)h;
    }
}

// ---------------------------------------------------------------------------
// W_o head-block sum + transpose + fp16
// ---------------------------------------------------------------------------
__global__ __launch_bounds__(256) void wosumT_k(const float* __restrict__ Wo,
                                                __half* __restrict__ T)
{
    __shared__ float t[32][33];
    int r0 = blockIdx.y * 32, c0 = blockIdx.x * 32;
    int tx = threadIdx.x & 31, ty = threadIdx.x >> 5;
#pragma unroll
    for (int i = 0; i < 4; i++) {
        int r = r0 + ty + i * 8;
        float s = 0.f;
#pragma unroll
        for (int h = 0; h < HH; h++)
            s += Wo[((size_t)(h * DD + r)) * DD + c0 + tx];
        t[ty + i * 8][tx] = s;
    }
    __syncthreads();
#pragma unroll
    for (int i = 0; i < 4; i++) {
        int cc = c0 + ty + i * 8;
        int rr = r0 + tx;
        T[(size_t)cc * DD + rr] = __float2half_rn(t[tx][ty + i * 8]);
    }
}

// ---------------------------------------------------------------------------
// Tensor-core causal flash attention (FA2 style), single-term fp16 Q/K/V/P.
// Work-balanced pairing: grid (NQB/2, H, B); CTA cc handles q-tiles
// (NQB-1-cc) then (cc) => exactly NQB+1 KV tiles per CTA (uniform).
// 128 threads (4 warps x 16 Q rows).
// ---------------------------------------------------------------------------
#define SMSA 144
#define ATILE 9216          // 64*144
#define ASM_TOTAL (5*ATILE) // 46080  (Q, K x2, V x2)

__global__ __launch_bounds__(128, 1) void attn_k(
    const __half* __restrict__ Qh,
    const __half* __restrict__ Kh, const __half* __restrict__ Vh,
    __half* __restrict__ oh)
{
    extern __shared__ char sm[];
    const uint32_t sb = smem_u32(sm);
    const int cc = blockIdx.x;                   // 0..NQB/2-1
    const int hh = blockIdx.y, bb = blockIdx.z;
    const int tid = threadIdx.x, lane = tid & 31, warp = tid >> 5;
    const size_t hbase = ((size_t)(bb*HH + hh)) * SS * 64;

    const uint32_t sQ  = sb;
    const uint32_t sK0 = sb + ATILE;
    const uint32_t sV0 = sb + 3*ATILE;

    const int rowg = lane >> 2;
    const int colg = (lane & 3) << 1;
    const uint32_t aoff = (warp*16 + (lane & 15))*SMSA + ((lane >> 4) << 4);

#pragma unroll 1
    for (int half = 0; half < 2; half++) {
        const int qb = half ? cc : (NQB - 1 - cc);

        // Q tile
        for (int idx = tid; idx < 512; idx += 128) {
            int r = idx >> 3, seg = idx & 7;
            size_t g = hbase + (size_t)(qb*64 + r)*64 + seg*8;
            CP16(sQ + r*SMSA + seg*16, (const uint4*)(Qh + g));
        }
        CP_COMMIT();

        auto loadKV = [&](int j) {
            uint32_t kb = sK0 + (j & 1)*ATILE;
            uint32_t vb = sV0 + (j & 1)*ATILE;
            for (int idx = tid; idx < 512; idx += 128) {
                int r = idx >> 3, seg = idx & 7;
                size_t g = hbase + (size_t)(j*64 + r)*64 + seg*8;
                CP16(kb + r*SMSA + seg*16, (const uint4*)(Kh + g));
                CP16(vb + r*SMSA + seg*16, (const uint4*)(Vh + g));
            }
            CP_COMMIT();
        };

        loadKV(0);

        uint32_t qf[4][4];
        float oacc[8][4];
        float m[2] = {-1e30f, -1e30f}, l[2] = {0.f, 0.f};
#pragma unroll
        for (int nt = 0; nt < 8; nt++)
#pragma unroll
            for (int j2 = 0; j2 < 4; j2++) oacc[nt][j2] = 0.f;

        for (int j = 0; j <= qb; j++) {
            if (j < qb) loadKV(j + 1);
            if (j < qb) CP_WAIT1(); else CP_WAIT0();
            __syncthreads();

            if (j == 0) {
#pragma unroll
                for (int kk = 0; kk < 4; kk++)
                    LDSM4(qf[kk], sQ + aoff + kk*32);
            }

            const uint32_t kb = sK0 + (j & 1)*ATILE;
            const uint32_t vb = sV0 + (j & 1)*ATILE;

            float sacc[8][4];
#pragma unroll
            for (int nt = 0; nt < 8; nt++)
#pragma unroll
                for (int j2 = 0; j2 < 4; j2++) sacc[nt][j2] = 0.f;

#pragma unroll
            for (int kk = 0; kk < 4; kk++) {
                uint32_t bf[16];
#pragma unroll
                for (int q = 0; q < 4; q++)
                    LDSM4(&bf[q*4], kb + (q*16 + (lane & 15))*SMSA
                                      + ((lane >> 4) << 4) + kk*32);
#pragma unroll
                for (int nt = 0; nt < 8; nt++) {
                    const int q = (nt >> 1)*4, r = nt & 1;
                    MMAH(sacc[nt], qf[kk], bf[q+r], bf[q+2+r]);
                }
            }

            const int grow0 = qb*64 + warp*16 + rowg;
#pragma unroll
            for (int nt = 0; nt < 8; nt++)
#pragma unroll
                for (int j2 = 0; j2 < 4; j2++) {
                    float s = sacc[nt][j2] * 0.125f;
                    if (j == qb) {
                        int gc = j*64 + nt*8 + colg + (j2 & 1);
                        int gr = grow0 + ((j2 >> 1) << 3);
                        if (gc > gr) s = -1e30f;
                    }
                    sacc[nt][j2] = s;
                }

            float mt[2] = {-1e30f, -1e30f};
#pragma unroll
            for (int nt = 0; nt < 8; nt++) {
                mt[0] = fmaxf(mt[0], fmaxf(sacc[nt][0], sacc[nt][1]));
                mt[1] = fmaxf(mt[1], fmaxf(sacc[nt][2], sacc[nt][3]));
            }
#pragma unroll
            for (int i = 0; i < 2; i++) {
                mt[i] = fmaxf(mt[i], __shfl_xor_sync(0xFFFFFFFFu, mt[i], 1));
                mt[i] = fmaxf(mt[i], __shfl_xor_sync(0xFFFFFFFFu, mt[i], 2));
            }
            float corr[2], mnew[2];
#pragma unroll
            for (int i = 0; i < 2; i++) {
                mnew[i] = fmaxf(m[i], mt[i]);
                corr[i] = __expf(m[i] - mnew[i]);
                m[i] = mnew[i];
            }
            float ls[2] = {0.f, 0.f};
#pragma unroll
            for (int nt = 0; nt < 8; nt++) {
                sacc[nt][0] = __expf(sacc[nt][0] - mnew[0]);
                sacc[nt][1] = __expf(sacc[nt][1] - mnew[0]);
                sacc[nt][2] = __expf(sacc[nt][2] - mnew[1]);
                sacc[nt][3] = __expf(sacc[nt][3] - mnew[1]);
                ls[0] += sacc[nt][0] + sacc[nt][1];
                ls[1] += sacc[nt][2] + sacc[nt][3];
            }
#pragma unroll
            for (int i = 0; i < 2; i++) {
                ls[i] += __shfl_xor_sync(0xFFFFFFFFu, ls[i], 1);
                ls[i] += __shfl_xor_sync(0xFFFFFFFFu, ls[i], 2);
                l[i] = l[i]*corr[i] + ls[i];
            }
#pragma unroll
            for (int nt = 0; nt < 8; nt++) {
                oacc[nt][0] *= corr[0]; oacc[nt][1] *= corr[0];
                oacc[nt][2] *= corr[1]; oacc[nt][3] *= corr[1];
            }

#pragma unroll
            for (int kt = 0; kt < 4; kt++) {
                uint32_t pa[4];
                pa[0] = f22u(sacc[2*kt  ][0], sacc[2*kt  ][1]);
                pa[1] = f22u(sacc[2*kt  ][2], sacc[2*kt  ][3]);
                pa[2] = f22u(sacc[2*kt+1][0], sacc[2*kt+1][1]);
                pa[3] = f22u(sacc[2*kt+1][2], sacc[2*kt+1][3]);
                uint32_t vf[16];
#pragma unroll
                for (int q = 0; q < 4; q++)
                    LDSM4T(&vf[q*4], vb + (kt*16 + (lane & 15))*SMSA
                                        + q*32 + ((lane >> 4) << 4));
#pragma unroll
                for (int nt = 0; nt < 8; nt++) {
                    const int base = (nt >> 1)*4 + ((nt & 1) << 1);
                    MMAH(oacc[nt], pa, vf[base], vf[base+1]);
                }
            }
            __syncthreads();
        }

        float inv[2] = {1.f / l[0], 1.f / l[1]};
#pragma unroll
        for (int nt = 0; nt < 8; nt++) {
            int srow0 = qb*64 + warp*16 + rowg;
            int col = hh*64 + nt*8 + colg;        // even -> half2 aligned
#pragma unroll
            for (int hr = 0; hr < 2; hr++) {
                int tok = bb*SS + srow0 + hr*8;
                __half2 hv = __floats2half2_rn(oacc[nt][hr*2] * inv[hr],
                                               oacc[nt][hr*2+1] * inv[hr]);
                *(__half2*)(oh + (size_t)tok*DD + col) = hv;
            }
        }
    }
}

// ---------------------------------------------------------------------------
// LayerNorm over D=768, optional fp32 out + fp16 out
// ---------------------------------------------------------------------------
__global__ __launch_bounds__(256) void layernorm_k(const float* __restrict__ X,
                                                   const float* __restrict__ g,
                                                   const float* __restrict__ b,
                                                   float* __restrict__ Y,
                                                   __half* __restrict__ Yh)
{
    int t = blockIdx.x;
    const float* xr = X + (size_t)t * DD;
    float vals[3];
    float s = 0.f, s2 = 0.f;
#pragma unroll
    for (int i = 0; i < 3; i++) {
        float v = xr[threadIdx.x + i * 256];
        vals[i] = v;
        s += v; s2 += v * v;
    }
#pragma unroll
    for (int o = 16; o > 0; o >>= 1) {
        s  += __shfl_xor_sync(0xFFFFFFFFu, s,  o);
        s2 += __shfl_xor_sync(0xFFFFFFFFu, s2, o);
    }
    __shared__ float rs[8], rs2[8];
    int w = threadIdx.x >> 5;
    if ((threadIdx.x & 31) == 0) { rs[w] = s; rs2[w] = s2; }
    __syncthreads();
    if (threadIdx.x < 32) {
        s  = (threadIdx.x < 8) ? rs [threadIdx.x] : 0.f;
        s2 = (threadIdx.x < 8) ? rs2[threadIdx.x] : 0.f;
#pragma unroll
        for (int o = 4; o > 0; o >>= 1) {
            s  += __shfl_xor_sync(0xFFFFFFFFu, s,  o);
            s2 += __shfl_xor_sync(0xFFFFFFFFu, s2, o);
        }
        if (threadIdx.x == 0) { rs[0] = s; rs2[0] = s2; }
    }
    __syncthreads();
    float mean = rs[0] * (1.f / DD);
    float var  = rs2[0] * (1.f / DD) - mean * mean;
    float rstd = rsqrtf(var + 1e-5f);
#pragma unroll
    for (int i = 0; i < 3; i++) {
        int d = threadIdx.x + i * 256;
        float v = (vals[i] - mean) * rstd * g[d] + b[d];
        size_t o = (size_t)t * DD + d;
        if (Y)  Y[o] = v;
        Yh[o] = __float2half_rn(v);
    }
}

// ---------------------------------------------------------------------------
// Launch
// ---------------------------------------------------------------------------
template<int MT>
static inline void run_gemm(const __half* Ah, const __half* Bt,
                            const float* bias, const float* Res,
                            float* C, __half* Ch, __half* K16, __half* V16,
                            int M, int N, int K, int mode)
{
    dim3 grid(M / (32*MT), (N + 127) / 128);
    int smem = 2 * (32*MT*SMS + 128*SMS);
    tgemm_k<MT><<<grid, 256, smem>>>((const uint4*)Ah, (const uint4*)Bt,
                                     bias, Res, C, Ch, K16, V16,
                                     M, N, K, mode);
}

extern "C" void kernel_launch(void* const* d_in, const int* in_sizes, int n_in,
                              void* d_out, int out_size)
{
    const int*   ids    = (const int*)  d_in[0];
    const float* emb    = (const float*)d_in[1];
    const float* W_qkv  = (const float*)d_in[2];
    const float* b_qkv  = (const float*)d_in[3];
    const float* W_o    = (const float*)d_in[4];
    const float* b_o    = (const float*)d_in[5];
    const float* ln1_g  = (const float*)d_in[6];
    const float* ln1_b  = (const float*)d_in[7];
    const float* W_ff1  = (const float*)d_in[8];
    const float* b_ff1  = (const float*)d_in[9];
    const float* W_ff2  = (const float*)d_in[10];
    const float* b_ff2  = (const float*)d_in[11];
    const float* ln2_g  = (const float*)d_in[12];
    const float* ln2_b  = (const float*)d_in[13];
    const float* W_out  = (const float*)d_in[14];
    const float* b_out  = (const float*)d_in[15];
    float* out = (float*)d_out;

    // Lazy one-time stream/event creation (outside graph capture: the
    // harness's first call is the correctness run).
    static cudaStream_t s2 = nullptr;
    static cudaEvent_t evFork, evWq, evWs, evW1, evW2, evWo;
    if (!s2) {
        cudaStreamCreateWithFlags(&s2, cudaStreamNonBlocking);
        cudaEventCreateWithFlags(&evFork, cudaEventDisableTiming);
        cudaEventCreateWithFlags(&evWq,   cudaEventDisableTiming);
        cudaEventCreateWithFlags(&evWs,   cudaEventDisableTiming);
        cudaEventCreateWithFlags(&evW1,   cudaEventDisableTiming);
        cudaEventCreateWithFlags(&evW2,   cudaEventDisableTiming);
        cudaEventCreateWithFlags(&evWo,   cudaEventDisableTiming);
        cudaFuncSetAttribute(tgemm_k<4>, cudaFuncAttributeMaxDynamicSharedMemorySize,
                             2*(128*SMS + 128*SMS));
        cudaFuncSetAttribute(tgemm_k<2>, cudaFuncAttributeMaxDynamicSharedMemorySize,
                             2*(64*SMS + 128*SMS));
        cudaFuncSetAttribute(attn_k, cudaFuncAttributeMaxDynamicSharedMemorySize,
                             ASM_TOTAL);
    }

    float *px, *pmha, *ph1, *pffo, *ppb;
    cudaGetSymbolAddress((void**)&px,   g_x);
    cudaGetSymbolAddress((void**)&pmha, g_mha);
    cudaGetSymbolAddress((void**)&ph1,  g_h1);
    cudaGetSymbolAddress((void**)&pffo, g_ffo);
    cudaGetSymbolAddress((void**)&ppb,  g_pebase);

    __half *xh,*ath,*h1h,*ffh,*h2h;
    cudaGetSymbolAddress((void**)&xh,  g_xh);
    cudaGetSymbolAddress((void**)&ath, g_ath);
    cudaGetSymbolAddress((void**)&h1h, g_h1h);
    cudaGetSymbolAddress((void**)&ffh, g_ffh);
    cudaGetSymbolAddress((void**)&h2h, g_h2h);

    __half *qh,*kh,*vh;
    cudaGetSymbolAddress((void**)&qh, g_qh);
    cudaGetSymbolAddress((void**)&kh, g_kh);
    cudaGetSymbolAddress((void**)&vh, g_vh);

    __half *wq,*ws,*w1,*w2,*wo;
    cudaGetSymbolAddress((void**)&wq, g_wqkvT);
    cudaGetSymbolAddress((void**)&ws, g_wsumT);
    cudaGetSymbolAddress((void**)&w1, g_wff1T);
    cudaGetSymbolAddress((void**)&w2, g_wff2T);
    cudaGetSymbolAddress((void**)&wo, g_woutT);

    // ---- fork: weight prep runs on s2, overlapped with the activation chain
    cudaEventRecord(evFork, 0);
    cudaStreamWaitEvent(s2, evFork, 0);

    wconvT_k<<<dim3((3*DD + 63)/64, DD/64), 256, 0, s2>>>(W_qkv, wq, DD, 3*DD);
    cudaEventRecord(evWq, s2);
    wosumT_k<<<dim3(DD/32, DD/32), 256, 0, s2>>>(W_o, ws);
    cudaEventRecord(evWs, s2);
    wconvT_k<<<dim3((FFD + 63)/64, DD/64), 256, 0, s2>>>(W_ff1, w1, DD, FFD);
    cudaEventRecord(evW1, s2);
    wconvT_k<<<dim3((DD + 63)/64, FFD/64), 256, 0, s2>>>(W_ff2, w2, FFD, DD);
    cudaEventRecord(evW2, s2);
    wconvT_k<<<dim3((VV + 63)/64, DD/64), 256, 0, s2>>>(W_out, wo, DD, VV);
    cudaEventRecord(evWo, s2);

    // ---- main chain (legacy stream)
    // 1. embeddings + PE
    pebase_k<<<3, 256>>>(ppb);
    embed_k<<<NTOK, 256>>>(ids, emb, ppb, px, xh);

    // 2. QKV projection -> head-major fp16 Q, K, V
    cudaStreamWaitEvent(0, evWq, 0);
    run_gemm<4>(xh, wq, b_qkv, nullptr,
                nullptr, qh, kh, vh,
                NTOK, 3*DD, DD, 1|8);

    // 3. tensor-core flash attention (work-balanced paired tiles)
    attn_k<<<dim3(NQB/2, HH, BB), 128, ASM_TOTAL>>>(qh, kh, vh, ath);

    // 4. mha = attn @ Wsum + b_o + x  (M64 tiles)
    cudaStreamWaitEvent(0, evWs, 0);
    run_gemm<2>(ath, ws, b_o, px,
                pmha, nullptr, nullptr, nullptr,
                NTOK, DD, DD, 1|4);

    // 5. LN1 (fp32 residual + fp16 out)
    layernorm_k<<<NTOK, 256>>>(pmha, ln1_g, ln1_b, ph1, h1h);

    // 6. FF1 + relu (fp16 out)
    cudaStreamWaitEvent(0, evW1, 0);
    run_gemm<4>(h1h, w1, b_ff1, nullptr,
                nullptr, ffh, nullptr, nullptr,
                NTOK, FFD, DD, 1|2);

    // 7. FF2 + residual (fp32 out; M64 tiles)
    cudaStreamWaitEvent(0, evW2, 0);
    run_gemm<2>(ffh, w2, b_ff2, ph1,
                pffo, nullptr, nullptr, nullptr,
                NTOK, DD, FFD, 1|4);

    // 8. LN2 (fp16 out)
    layernorm_k<<<NTOK, 256>>>(pffo, ln2_g, ln2_b, nullptr, h2h);

    // 9. vocab projection (join: W_out convert must be done)
    cudaStreamWaitEvent(0, evWo, 0);
    run_gemm<4>(h2h, wo, b_out, nullptr,
                out, nullptr, nullptr, nullptr,
                NTOK, VV, DD, 1);
}

// round 15
// speedup vs baseline: 1.2856x; 1.0125x over previous
#include <cuda_runtime.h>
#include <cuda_fp16.h>
#include <math.h>
#include <stdint.h>

// Problem constants
#define BB   2
#define SS   2048
#define DD   768
#define HH   12
#define VV   50257
#define FFD  3072
#define HDIM 64
#define NTOK (BB*SS)
#define HTOK SS             // tokens per batch half
#define NQB  (SS/64)        // 32 q-tiles per (b,h)

// ---------------------------------------------------------------------------
// Scratch (static device globals -- no allocation allowed)
// ---------------------------------------------------------------------------
__device__ float g_x   [NTOK*DD];
__device__ float g_mha [NTOK*DD];
__device__ float g_h1  [NTOK*DD];
__device__ float g_ffo [NTOK*DD];
__device__ float g_pebase[DD];

// fp16 activations
__device__ __half g_xh [NTOK*DD];
__device__ __half g_ath[NTOK*DD];
__device__ __half g_h1h[NTOK*DD];
__device__ __half g_ffh[NTOK*FFD];
__device__ __half g_h2h[NTOK*DD];

// head-major attention operands [b][h][s][64]
__device__ __half g_qh[NTOK*DD];
__device__ __half g_kh[NTOK*DD];
__device__ __half g_vh[NTOK*DD];

// fp16 transposed weights [N,K]
__device__ __half g_wqkvT[3*DD*DD];
__device__ __half g_wsumT[DD*DD];
__device__ __half g_wff1T[(size_t)FFD*DD];
__device__ __half g_wff2T[(size_t)DD*FFD];
__device__ __half g_woutT[(size_t)VV*DD];

// ---------------------------------------------------------------------------
// PTX helpers (plain sm_103-safe: cp.async, ldmatrix, mma.sync only)
// ---------------------------------------------------------------------------
__device__ __forceinline__ uint32_t smem_u32(const void* p) {
    uint32_t a;
    asm("{ .reg .u64 t; cvta.to.shared.u64 t, %1; cvt.u32.u64 %0, t; }"
        : "=r"(a) : "l"(p));
    return a;
}

#define CP16(dst, src) \
    asm volatile("cp.async.cg.shared.global [%0], [%1], 16;" \
                 :: "r"(dst), "l"(src) : "memory")
#define CP_COMMIT() asm volatile("cp.async.commit_group;" ::: "memory")
#define CP_WAIT1()  asm volatile("cp.async.wait_group 1;"  ::: "memory")
#define CP_WAIT0()  asm volatile("cp.async.wait_group 0;"  ::: "memory")

#define LDSM4(r, a) \
    asm volatile("ldmatrix.sync.aligned.m8n8.x4.shared.b16 {%0,%1,%2,%3}, [%4];" \
        : "=r"((r)[0]), "=r"((r)[1]), "=r"((r)[2]), "=r"((r)[3]) : "r"(a))

#define LDSM4T(r, a) \
    asm volatile("ldmatrix.sync.aligned.m8n8.x4.trans.shared.b16 {%0,%1,%2,%3}, [%4];" \
        : "=r"((r)[0]), "=r"((r)[1]), "=r"((r)[2]), "=r"((r)[3]) : "r"(a))

#define MMAH(d, a, b0, b1) \
    asm volatile("mma.sync.aligned.m16n8k16.row.col.f32.f16.f16.f32 " \
        "{%0,%1,%2,%3}, {%4,%5,%6,%7}, {%8,%9}, {%0,%1,%2,%3};" \
        : "+f"((d)[0]), "+f"((d)[1]), "+f"((d)[2]), "+f"((d)[3]) \
        : "r"((a)[0]), "r"((a)[1]), "r"((a)[2]), "r"((a)[3]), \
          "r"(b0), "r"(b1))

__device__ __forceinline__ uint32_t f22u(float a, float b) {
    __half2 t = __floats2half2_rn(a, b);
    return *reinterpret_cast<uint32_t*>(&t);
}

// ---------------------------------------------------------------------------
// Single-term fp16 mma.sync GEMM: C[M,N] = A[M,K] @ Bt[N,K]^T
// MT = per-warp m-subtiles (4 -> CTA 128xN, 2 -> CTA 64xN). 8 warps, BK=32.
// tok0: absolute token offset of row 0 (for mode8 head-major scatter).
// mode: 1=+bias, 2=relu, 4=+Res, 8=QKV head-major scatter
// ---------------------------------------------------------------------------
#define SMS 80

template<int MT>
__global__ __launch_bounds__(256, 2) void tgemm_k(
    const uint4* __restrict__ Ah, const uint4* __restrict__ Bt,
    const float* __restrict__ bias, const float* __restrict__ Res,
    float* __restrict__ C, __half* __restrict__ Ch,
    __half* __restrict__ K16, __half* __restrict__ V16,
    int M, int N, int K, int mode, int tok0)
{
    constexpr int ABY = 32*MT*SMS;
    constexpr int BUF = ABY + 128*SMS;

    extern __shared__ char sm[];
    const uint32_t sb = smem_u32(sm);
    const int tid  = threadIdx.x;
    const int lane = tid & 31;
    const int warp = tid >> 5;
    const int wm = warp >> 2;
    const int wn = warp & 3;
    const int m0 = blockIdx.x * (32*MT);
    const int n0 = blockIdx.y * 128;

    const int Kv  = K >> 3;
    const int nch = K >> 5;
    const int lrow = tid >> 2;
    const int lseg = tid & 3;

    float acc[MT][4][4];
#pragma unroll
    for (int i = 0; i < MT; i++)
#pragma unroll
        for (int j = 0; j < 4; j++)
#pragma unroll
            for (int k = 0; k < 4; k++) acc[i][j][k] = 0.f;

    auto load_chunk = [&](int c) {
        const int b = c & 1;
        const uint32_t base = sb + b * BUF;
        const int kc4 = c << 2;
#pragma unroll
        for (int it = 0; it < MT/2; it++) {
            int row = lrow + it * 64;
            size_t ga = (size_t)(m0 + row) * Kv + kc4 + lseg;
            CP16(base + row * SMS + lseg * 16, Ah + ga);
        }
#pragma unroll
        for (int it = 0; it < 2; it++) {
            int row = lrow + it * 64;
            int rn = n0 + row; if (rn >= N) rn = N - 1;
            size_t gb = (size_t)rn * Kv + kc4 + lseg;
            CP16(base + ABY + row * SMS + lseg * 16, Bt + gb);
        }
        CP_COMMIT();
    };

    load_chunk(0);

    for (int c = 0; c < nch; c++) {
        if (c + 1 < nch) { load_chunk(c + 1); CP_WAIT1(); }
        else             { CP_WAIT0(); }
        __syncthreads();

        const uint32_t base = sb + (c & 1) * BUF;
        const uint32_t ab = base + (wm * (16*MT) + (lane & 15)) * SMS + ((lane >> 4) << 4);
        const uint32_t bb = base + ABY + (wn * 32 + (lane & 15)) * SMS + ((lane >> 4) << 4);

#pragma unroll
        for (int ks = 0; ks < 2; ks++) {
            const uint32_t ko = ks << 5;
            uint32_t ahf[MT*4], bf[8];
#pragma unroll
            for (int mt = 0; mt < MT; mt++)
                LDSM4(&ahf[mt*4], ab + mt * (16*SMS) + ko);
#pragma unroll
            for (int q = 0; q < 2; q++)
                LDSM4(&bf[q*4], bb + q * (16*SMS) + ko);
#pragma unroll
            for (int mt = 0; mt < MT; mt++)
#pragma unroll
                for (int nt = 0; nt < 4; nt++) {
                    const int q = (nt >> 1) * 4, r = nt & 1;
                    MMAH(acc[mt][nt], &ahf[mt*4], bf[q+r], bf[q+2+r]);
                }
        }
        __syncthreads();
    }

    // epilogue (vectorized half2 where possible)
#pragma unroll
    for (int mt = 0; mt < MT; mt++) {
        const int row0 = m0 + wm * (16*MT) + mt * 16 + (lane >> 2);
#pragma unroll
        for (int nt = 0; nt < 4; nt++) {
            const int col = n0 + wn * 32 + nt * 8 + ((lane & 3) << 1);
            if (col >= N) continue;
            const bool pair = (col + 1 < N);
            const float* d = acc[mt][nt];
#pragma unroll
            for (int h = 0; h < 2; h++) {
                const int r = row0 + h * 8;
                size_t o = (size_t)r * N + col;
                float v0 = d[h*2+0], v1 = d[h*2+1];
                if (mode & 1) { v0 += bias[col]; if (pair) v1 += bias[col+1]; }
                if (mode & 4) { v0 += Res[o];    if (pair) v1 += Res[o+1]; }
                if (mode & 2) { v0 = fmaxf(v0, 0.f); v1 = fmaxf(v1, 0.f); }
                if (mode & 8) {
                    int t = tok0 + r;
                    int bq = t >> 11, sq = t & 2047;
                    int part = col / DD;          // 0=Q 1=K 2=V
                    int cd = col - part * DD;
                    int hd = cd >> 6, dd = cd & 63;
                    size_t oo = (((size_t)(bq*HH + hd))*SS + sq)*64 + dd;
                    __half2 hv = __floats2half2_rn(v0, v1);
                    __half* dst = (part == 0) ? Ch : (part == 1) ? K16 : V16;
                    *(__half2*)(dst + oo) = hv;
                } else {
                    if (C) {
                        C[o] = v0;
                        if (pair) C[o+1] = v1;
                    }
                    if (Ch) {
                        if (pair) *(__half2*)(Ch + o) = __floats2half2_rn(v0, v1);
                        else      Ch[o] = __float2half_rn(v0);
                    }
                }
            }
        }
    }
}

// ---------------------------------------------------------------------------
// PE frequency table:  pebase[d] = 10000^(-2d/D)
// ---------------------------------------------------------------------------
__global__ void pebase_k(float* __restrict__ pb)
{
    int d = blockIdx.x * 256 + threadIdx.x;
    if (d < DD) pb[d] = powf(10000.0f, -2.0f * (float)d / (float)DD);
}

// ---------------------------------------------------------------------------
// Embedding + positional encoding, fused fp16 convert; tok0 = token offset
// ---------------------------------------------------------------------------
__global__ __launch_bounds__(256) void embed_k(const int* __restrict__ ids,
                                               const float* __restrict__ emb,
                                               const float* __restrict__ pb,
                                               float* __restrict__ x,
                                               __half* __restrict__ xh,
                                               int tok0)
{
    int t = tok0 + blockIdx.x;
    int s = t % SS;
    int id = ids[t];
    const float* er = emb + (size_t)id * DD;
    size_t base = (size_t)t * DD;
    for (int d = threadIdx.x; d < DD; d += 256) {
        float ang = (float)s * pb[d];
        float pe  = (d & 1) ? cosf(ang) : sinf(ang);
        float v = er[d] + pe;
        x[base + d] = v;
        xh[base + d] = __float2half_rn(v);
    }
}

// ---------------------------------------------------------------------------
// Weight transpose + fp16 convert: W[K,N] -> T[N,K]
// ---------------------------------------------------------------------------
__global__ __launch_bounds__(256) void wconvT_k(const float* __restrict__ W,
                                                __half* __restrict__ T,
                                                int K, int N)
{
    __shared__ float t[64][65];
    const int k0 = blockIdx.y * 64, n0 = blockIdx.x * 64;
    const int tid = threadIdx.x;

#pragma unroll
    for (int it = 0; it < 16; it++) {
        int i = tid + it * 256;
        int r = i >> 6, c = i & 63;
        int n = n0 + c;
        t[r][c] = (n < N) ? W[(size_t)(k0 + r) * N + n] : 0.f;
    }
    __syncthreads();

#pragma unroll
    for (int it = 0; it < 2; it++) {
        int i = tid + it * 256;
        int n = i >> 3, kc = (i & 7) << 3;
        if (n0 + n >= N) continue;
        __half h[8];
#pragma unroll
        for (int j = 0; j < 8; j++) h[j] = __float2half_rn(t[kc + j][n]);
        *(uint4*)&T[(size_t)(n0 + n) * K + k0 + kc] = *(uint4*)h;
    }
}

// ---------------------------------------------------------------------------
// W_o head-block sum + transpose + fp16
// ---------------------------------------------------------------------------
__global__ __launch_bounds__(256) void wosumT_k(const float* __restrict__ Wo,
                                                __half* __restrict__ T)
{
    __shared__ float t[32][33];
    int r0 = blockIdx.y * 32, c0 = blockIdx.x * 32;
    int tx = threadIdx.x & 31, ty = threadIdx.x >> 5;
#pragma unroll
    for (int i = 0; i < 4; i++) {
        int r = r0 + ty + i * 8;
        float s = 0.f;
#pragma unroll
        for (int h = 0; h < HH; h++)
            s += Wo[((size_t)(h * DD + r)) * DD + c0 + tx];
        t[ty + i * 8][tx] = s;
    }
    __syncthreads();
#pragma unroll
    for (int i = 0; i < 4; i++) {
        int cc = c0 + ty + i * 8;
        int rr = r0 + tx;
        T[(size_t)cc * DD + rr] = __float2half_rn(t[tx][ty + i * 8]);
    }
}

// ---------------------------------------------------------------------------
// Tensor-core causal flash attention, single-term fp16 Q/K/V/P.
// Work-balanced pairing; per-batch launch: grid (NQB/2, H), bb passed in.
// ---------------------------------------------------------------------------
#define SMSA 144
#define ATILE 9216
#define ASM_TOTAL (5*ATILE)

__global__ __launch_bounds__(128, 1) void attn_k(
    const __half* __restrict__ Qh,
    const __half* __restrict__ Kh, const __half* __restrict__ Vh,
    __half* __restrict__ oh, int bb)
{
    extern __shared__ char sm[];
    const uint32_t sb = smem_u32(sm);
    const int cc = blockIdx.x;
    const int hh = blockIdx.y;
    const int tid = threadIdx.x, lane = tid & 31, warp = tid >> 5;
    const size_t hbase = ((size_t)(bb*HH + hh)) * SS * 64;

    const uint32_t sQ  = sb;
    const uint32_t sK0 = sb + ATILE;
    const uint32_t sV0 = sb + 3*ATILE;

    const int rowg = lane >> 2;
    const int colg = (lane & 3) << 1;
    const uint32_t aoff = (warp*16 + (lane & 15))*SMSA + ((lane >> 4) << 4);

#pragma unroll 1
    for (int half = 0; half < 2; half++) {
        const int qb = half ? cc : (NQB - 1 - cc);

        for (int idx = tid; idx < 512; idx += 128) {
            int r = idx >> 3, seg = idx & 7;
            size_t g = hbase + (size_t)(qb*64 + r)*64 + seg*8;
            CP16(sQ + r*SMSA + seg*16, (const uint4*)(Qh + g));
        }
        CP_COMMIT();

        auto loadKV = [&](int j) {
            uint32_t kb = sK0 + (j & 1)*ATILE;
            uint32_t vb = sV0 + (j & 1)*ATILE;
            for (int idx = tid; idx < 512; idx += 128) {
                int r = idx >> 3, seg = idx & 7;
                size_t g = hbase + (size_t)(j*64 + r)*64 + seg*8;
                CP16(kb + r*SMSA + seg*16, (const uint4*)(Kh + g));
                CP16(vb + r*SMSA + seg*16, (const uint4*)(Vh + g));
            }
            CP_COMMIT();
        };

        loadKV(0);

        uint32_t qf[4][4];
        float oacc[8][4];
        float m[2] = {-1e30f, -1e30f}, l[2] = {0.f, 0.f};
#pragma unroll
        for (int nt = 0; nt < 8; nt++)
#pragma unroll
            for (int j2 = 0; j2 < 4; j2++) oacc[nt][j2] = 0.f;

        for (int j = 0; j <= qb; j++) {
            if (j < qb) loadKV(j + 1);
            if (j < qb) CP_WAIT1(); else CP_WAIT0();
            __syncthreads();

            if (j == 0) {
#pragma unroll
                for (int kk = 0; kk < 4; kk++)
                    LDSM4(qf[kk], sQ + aoff + kk*32);
            }

            const uint32_t kb = sK0 + (j & 1)*ATILE;
            const uint32_t vb = sV0 + (j & 1)*ATILE;

            float sacc[8][4];
#pragma unroll
            for (int nt = 0; nt < 8; nt++)
#pragma unroll
                for (int j2 = 0; j2 < 4; j2++) sacc[nt][j2] = 0.f;

#pragma unroll
            for (int kk = 0; kk < 4; kk++) {
                uint32_t bf[16];
#pragma unroll
                for (int q = 0; q < 4; q++)
                    LDSM4(&bf[q*4], kb + (q*16 + (lane & 15))*SMSA
                                      + ((lane >> 4) << 4) + kk*32);
#pragma unroll
                for (int nt = 0; nt < 8; nt++) {
                    const int q = (nt >> 1)*4, r = nt & 1;
                    MMAH(sacc[nt], qf[kk], bf[q+r], bf[q+2+r]);
                }
            }

            const int grow0 = qb*64 + warp*16 + rowg;
#pragma unroll
            for (int nt = 0; nt < 8; nt++)
#pragma unroll
                for (int j2 = 0; j2 < 4; j2++) {
                    float s = sacc[nt][j2] * 0.125f;
                    if (j == qb) {
                        int gc = j*64 + nt*8 + colg + (j2 & 1);
                        int gr = grow0 + ((j2 >> 1) << 3);
                        if (gc > gr) s = -1e30f;
                    }
                    sacc[nt][j2] = s;
                }

            float mt[2] = {-1e30f, -1e30f};
#pragma unroll
            for (int nt = 0; nt < 8; nt++) {
                mt[0] = fmaxf(mt[0], fmaxf(sacc[nt][0], sacc[nt][1]));
                mt[1] = fmaxf(mt[1], fmaxf(sacc[nt][2], sacc[nt][3]));
            }
#pragma unroll
            for (int i = 0; i < 2; i++) {
                mt[i] = fmaxf(mt[i], __shfl_xor_sync(0xFFFFFFFFu, mt[i], 1));
                mt[i] = fmaxf(mt[i], __shfl_xor_sync(0xFFFFFFFFu, mt[i], 2));
            }
            float corr[2], mnew[2];
#pragma unroll
            for (int i = 0; i < 2; i++) {
                mnew[i] = fmaxf(m[i], mt[i]);
                corr[i] = __expf(m[i] - mnew[i]);
                m[i] = mnew[i];
            }
            float ls[2] = {0.f, 0.f};
#pragma unroll
            for (int nt = 0; nt < 8; nt++) {
                sacc[nt][0] = __expf(sacc[nt][0] - mnew[0]);
                sacc[nt][1] = __expf(sacc[nt][1] - mnew[0]);
                sacc[nt][2] = __expf(sacc[nt][2] - mnew[1]);
                sacc[nt][3] = __expf(sacc[nt][3] - mnew[1]);
                ls[0] += sacc[nt][0] + sacc[nt][1];
                ls[1] += sacc[nt][2] + sacc[nt][3];
            }
#pragma unroll
            for (int i = 0; i < 2; i++) {
                ls[i] += __shfl_xor_sync(0xFFFFFFFFu, ls[i], 1);
                ls[i] += __shfl_xor_sync(0xFFFFFFFFu, ls[i], 2);
                l[i] = l[i]*corr[i] + ls[i];
            }
#pragma unroll
            for (int nt = 0; nt < 8; nt++) {
                oacc[nt][0] *= corr[0]; oacc[nt][1] *= corr[0];
                oacc[nt][2] *= corr[1]; oacc[nt][3] *= corr[1];
            }

#pragma unroll
            for (int kt = 0; kt < 4; kt++) {
                uint32_t pa[4];
                pa[0] = f22u(sacc[2*kt  ][0], sacc[2*kt  ][1]);
                pa[1] = f22u(sacc[2*kt  ][2], sacc[2*kt  ][3]);
                pa[2] = f22u(sacc[2*kt+1][0], sacc[2*kt+1][1]);
                pa[3] = f22u(sacc[2*kt+1][2], sacc[2*kt+1][3]);
                uint32_t vf[16];
#pragma unroll
                for (int q = 0; q < 4; q++)
                    LDSM4T(&vf[q*4], vb + (kt*16 + (lane & 15))*SMSA
                                        + q*32 + ((lane >> 4) << 4));
#pragma unroll
                for (int nt = 0; nt < 8; nt++) {
                    const int base = (nt >> 1)*4 + ((nt & 1) << 1);
                    MMAH(oacc[nt], pa, vf[base], vf[base+1]);
                }
            }
            __syncthreads();
        }

        float inv[2] = {1.f / l[0], 1.f / l[1]};
#pragma unroll
        for (int nt = 0; nt < 8; nt++) {
            int srow0 = qb*64 + warp*16 + rowg;
            int col = hh*64 + nt*8 + colg;
#pragma unroll
            for (int hr = 0; hr < 2; hr++) {
                int tok = bb*SS + srow0 + hr*8;
                __half2 hv = __floats2half2_rn(oacc[nt][hr*2] * inv[hr],
                                               oacc[nt][hr*2+1] * inv[hr]);
                *(__half2*)(oh + (size_t)tok*DD + col) = hv;
            }
        }
    }
}

// ---------------------------------------------------------------------------
// LayerNorm over D=768 (per-row; pointer-offset for batch halves)
// ---------------------------------------------------------------------------
__global__ __launch_bounds__(256) void layernorm_k(const float* __restrict__ X,
                                                   const float* __restrict__ g,
                                                   const float* __restrict__ b,
                                                   float* __restrict__ Y,
                                                   __half* __restrict__ Yh)
{
    int t = blockIdx.x;
    const float* xr = X + (size_t)t * DD;
    float vals[3];
    float s = 0.f, s2 = 0.f;
#pragma unroll
    for (int i = 0; i < 3; i++) {
        float v = xr[threadIdx.x + i * 256];
        vals[i] = v;
        s += v; s2 += v * v;
    }
#pragma unroll
    for (int o = 16; o > 0; o >>= 1) {
        s  += __shfl_xor_sync(0xFFFFFFFFu, s,  o);
        s2 += __shfl_xor_sync(0xFFFFFFFFu, s2, o);
    }
    __shared__ float rs[8], rs2[8];
    int w = threadIdx.x >> 5;
    if ((threadIdx.x & 31) == 0) { rs[w] = s; rs2[w] = s2; }
    __syncthreads();
    if (threadIdx.x < 32) {
        s  = (threadIdx.x < 8) ? rs [threadIdx.x] : 0.f;
        s2 = (threadIdx.x < 8) ? rs2[threadIdx.x] : 0.f;
#pragma unroll
        for (int o = 4; o > 0; o >>= 1) {
            s  += __shfl_xor_sync(0xFFFFFFFFu, s,  o);
            s2 += __shfl_xor_sync(0xFFFFFFFFu, s2, o);
        }
        if (threadIdx.x == 0) { rs[0] = s; rs2[0] = s2; }
    }
    __syncthreads();
    float mean = rs[0] * (1.f / DD);
    float var  = rs2[0] * (1.f / DD) - mean * mean;
    float rstd = rsqrtf(var + 1e-5f);
#pragma unroll
    for (int i = 0; i < 3; i++) {
        int d = threadIdx.x + i * 256;
        float v = (vals[i] - mean) * rstd * g[d] + b[d];
        size_t o = (size_t)t * DD + d;
        if (Y)  Y[o] = v;
        Yh[o] = __float2half_rn(v);
    }
}

// ---------------------------------------------------------------------------
// Launch
// ---------------------------------------------------------------------------
template<int MT>
static inline void run_gemm(cudaStream_t st,
                            const __half* Ah, const __half* Bt,
                            const float* bias, const float* Res,
                            float* C, __half* Ch, __half* K16, __half* V16,
                            int M, int N, int K, int mode, int tok0)
{
    dim3 grid(M / (32*MT), (N + 127) / 128);
    int smem = 2 * (32*MT*SMS + 128*SMS);
    tgemm_k<MT><<<grid, 256, smem, st>>>((const uint4*)Ah, (const uint4*)Bt,
                                         bias, Res, C, Ch, K16, V16,
                                         M, N, K, mode, tok0);
}

extern "C" void kernel_launch(void* const* d_in, const int* in_sizes, int n_in,
                              void* d_out, int out_size)
{
    const int*   ids    = (const int*)  d_in[0];
    const float* emb    = (const float*)d_in[1];
    const float* W_qkv  = (const float*)d_in[2];
    const float* b_qkv  = (const float*)d_in[3];
    const float* W_o    = (const float*)d_in[4];
    const float* b_o    = (const float*)d_in[5];
    const float* ln1_g  = (const float*)d_in[6];
    const float* ln1_b  = (const float*)d_in[7];
    const float* W_ff1  = (const float*)d_in[8];
    const float* b_ff1  = (const float*)d_in[9];
    const float* W_ff2  = (const float*)d_in[10];
    const float* b_ff2  = (const float*)d_in[11];
    const float* ln2_g  = (const float*)d_in[12];
    const float* ln2_b  = (const float*)d_in[13];
    const float* W_out  = (const float*)d_in[14];
    const float* b_out  = (const float*)d_in[15];
    float* out = (float*)d_out;

    static cudaStream_t s2 = nullptr, s3 = nullptr;
    static cudaEvent_t evFork, evPE, evWq, evWs, evW1, evW2, evWo, evB;
    if (!s2) {
        cudaStreamCreateWithFlags(&s2, cudaStreamNonBlocking);
        cudaStreamCreateWithFlags(&s3, cudaStreamNonBlocking);
        cudaEventCreateWithFlags(&evFork, cudaEventDisableTiming);
        cudaEventCreateWithFlags(&evPE,   cudaEventDisableTiming);
        cudaEventCreateWithFlags(&evWq,   cudaEventDisableTiming);
        cudaEventCreateWithFlags(&evWs,   cudaEventDisableTiming);
        cudaEventCreateWithFlags(&evW1,   cudaEventDisableTiming);
        cudaEventCreateWithFlags(&evW2,   cudaEventDisableTiming);
        cudaEventCreateWithFlags(&evWo,   cudaEventDisableTiming);
        cudaEventCreateWithFlags(&evB,    cudaEventDisableTiming);
        cudaFuncSetAttribute(tgemm_k<4>, cudaFuncAttributeMaxDynamicSharedMemorySize,
                             2*(128*SMS + 128*SMS));
        cudaFuncSetAttribute(tgemm_k<2>, cudaFuncAttributeMaxDynamicSharedMemorySize,
                             2*(64*SMS + 128*SMS));
        cudaFuncSetAttribute(attn_k, cudaFuncAttributeMaxDynamicSharedMemorySize,
                             ASM_TOTAL);
    }

    float *px, *pmha, *ph1, *pffo, *ppb;
    cudaGetSymbolAddress((void**)&px,   g_x);
    cudaGetSymbolAddress((void**)&pmha, g_mha);
    cudaGetSymbolAddress((void**)&ph1,  g_h1);
    cudaGetSymbolAddress((void**)&pffo, g_ffo);
    cudaGetSymbolAddress((void**)&ppb,  g_pebase);

    __half *xh,*ath,*h1h,*ffh,*h2h;
    cudaGetSymbolAddress((void**)&xh,  g_xh);
    cudaGetSymbolAddress((void**)&ath, g_ath);
    cudaGetSymbolAddress((void**)&h1h, g_h1h);
    cudaGetSymbolAddress((void**)&ffh, g_ffh);
    cudaGetSymbolAddress((void**)&h2h, g_h2h);

    __half *qh,*kh,*vh;
    cudaGetSymbolAddress((void**)&qh, g_qh);
    cudaGetSymbolAddress((void**)&kh, g_kh);
    cudaGetSymbolAddress((void**)&vh, g_vh);

    __half *wq,*ws,*w1,*w2,*wo;
    cudaGetSymbolAddress((void**)&wq, g_wqkvT);
    cudaGetSymbolAddress((void**)&ws, g_wsumT);
    cudaGetSymbolAddress((void**)&w1, g_wff1T);
    cudaGetSymbolAddress((void**)&w2, g_wff2T);
    cudaGetSymbolAddress((void**)&wo, g_woutT);

    // ---- fork prep (s2) and batch-1 (s3) streams from legacy
    cudaEventRecord(evFork, 0);
    cudaStreamWaitEvent(s2, evFork, 0);
    cudaStreamWaitEvent(s3, evFork, 0);

    // weight prep on s2
    wconvT_k<<<dim3((3*DD + 63)/64, DD/64), 256, 0, s2>>>(W_qkv, wq, DD, 3*DD);
    cudaEventRecord(evWq, s2);
    wosumT_k<<<dim3(DD/32, DD/32), 256, 0, s2>>>(W_o, ws);
    cudaEventRecord(evWs, s2);
    wconvT_k<<<dim3((FFD + 63)/64, DD/64), 256, 0, s2>>>(W_ff1, w1, DD, FFD);
    cudaEventRecord(evW1, s2);
    wconvT_k<<<dim3((DD + 63)/64, FFD/64), 256, 0, s2>>>(W_ff2, w2, FFD, DD);
    cudaEventRecord(evW2, s2);
    wconvT_k<<<dim3((VV + 63)/64, DD/64), 256, 0, s2>>>(W_out, wo, DD, VV);
    cudaEventRecord(evWo, s2);

    // PE table on legacy, visible to s3
    pebase_k<<<3, 256>>>(ppb);
    cudaEventRecord(evPE, 0);
    cudaStreamWaitEvent(s3, evPE, 0);

    const int T0 = 0, T1 = HTOK;   // batch halves
    #define OFF32(p, t) ((p) + (size_t)(t)*DD)
    #define OFF16(p, t) ((p) + (size_t)(t)*DD)

    // 1. embeddings
    embed_k<<<HTOK, 256, 0, 0 >>>(ids, emb, ppb, px, xh, T0);
    embed_k<<<HTOK, 256, 0, s3>>>(ids, emb, ppb, px, xh, T1);

    // 2. QKV projection -> head-major fp16 Q, K, V
    cudaStreamWaitEvent(0,  evWq, 0);
    cudaStreamWaitEvent(s3, evWq, 0);
    run_gemm<4>(0,  OFF16(xh,T0), wq, b_qkv, nullptr,
                nullptr, qh, kh, vh, HTOK, 3*DD, DD, 1|8, T0);
    run_gemm<4>(s3, OFF16(xh,T1), wq, b_qkv, nullptr,
                nullptr, qh, kh, vh, HTOK, 3*DD, DD, 1|8, T1);

    // 3. attention (per batch)
    attn_k<<<dim3(NQB/2, HH), 128, ASM_TOTAL, 0 >>>(qh, kh, vh, ath, 0);
    attn_k<<<dim3(NQB/2, HH), 128, ASM_TOTAL, s3>>>(qh, kh, vh, ath, 1);

    // 4. mha = attn @ Wsum + b_o + x
    cudaStreamWaitEvent(0,  evWs, 0);
    cudaStreamWaitEvent(s3, evWs, 0);
    run_gemm<2>(0,  OFF16(ath,T0), ws, b_o, OFF32(px,T0),
                OFF32(pmha,T0), nullptr, nullptr, nullptr,
                HTOK, DD, DD, 1|4, T0);
    run_gemm<2>(s3, OFF16(ath,T1), ws, b_o, OFF32(px,T1),
                OFF32(pmha,T1), nullptr, nullptr, nullptr,
                HTOK, DD, DD, 1|4, T1);

    // 5. LN1
    layernorm_k<<<HTOK, 256, 0, 0 >>>(OFF32(pmha,T0), ln1_g, ln1_b,
                                      OFF32(ph1,T0), OFF16(h1h,T0));
    layernorm_k<<<HTOK, 256, 0, s3>>>(OFF32(pmha,T1), ln1_g, ln1_b,
                                      OFF32(ph1,T1), OFF16(h1h,T1));

    // 6. FF1 + relu
    cudaStreamWaitEvent(0,  evW1, 0);
    cudaStreamWaitEvent(s3, evW1, 0);
    run_gemm<4>(0,  OFF16(h1h,T0), w1, b_ff1, nullptr,
                nullptr, ffh + (size_t)T0*FFD, nullptr, nullptr,
                HTOK, FFD, DD, 1|2, T0);
    run_gemm<4>(s3, OFF16(h1h,T1), w1, b_ff1, nullptr,
                nullptr, ffh + (size_t)T1*FFD, nullptr, nullptr,
                HTOK, FFD, DD, 1|2, T1);

    // 7. FF2 + residual
    cudaStreamWaitEvent(0,  evW2, 0);
    cudaStreamWaitEvent(s3, evW2, 0);
    run_gemm<2>(0,  ffh + (size_t)T0*FFD, w2, b_ff2, OFF32(ph1,T0),
                OFF32(pffo,T0), nullptr, nullptr, nullptr,
                HTOK, DD, FFD, 1|4, T0);
    run_gemm<2>(s3, ffh + (size_t)T1*FFD, w2, b_ff2, OFF32(ph1,T1),
                OFF32(pffo,T1), nullptr, nullptr, nullptr,
                HTOK, DD, FFD, 1|4, T1);

    // 8. LN2
    layernorm_k<<<HTOK, 256, 0, 0 >>>(OFF32(pffo,T0), ln2_g, ln2_b,
                                      nullptr, OFF16(h2h,T0));
    layernorm_k<<<HTOK, 256, 0, s3>>>(OFF32(pffo,T1), ln2_g, ln2_b,
                                      nullptr, OFF16(h2h,T1));

    // 9. vocab projection
    cudaStreamWaitEvent(0,  evWo, 0);
    cudaStreamWaitEvent(s3, evWo, 0);
    run_gemm<4>(0,  OFF16(h2h,T0), wo, b_out, nullptr,
                out + (size_t)T0*VV, nullptr, nullptr, nullptr,
                HTOK, VV, DD, 1, T0);
    run_gemm<4>(s3, OFF16(h2h,T1), wo, b_out, nullptr,
                out + (size_t)T1*VV, nullptr, nullptr, nullptr,
                HTOK, VV, DD, 1, T1);

    // join batch-1 stream back into legacy before capture ends
    cudaEventRecord(evB, s3);
    cudaStreamWaitEvent(0, evB, 0);
}